// round 13
// baseline (speedup 1.0000x reference)
#include <cuda_runtime.h>
#include <cuda_bf16.h>
#include <cstdint>
#include <cstddef>

#define N_NODES 200000
#define C 128
#define S 6
#define EP 100000
#define EL 25000
#define CC 16384

typedef unsigned long long u64;
typedef unsigned int u32;

// ---- static device scratch ----
__device__ float g_T[(size_t)N_NODES * C];
__device__ __nv_bfloat16 g_Fhl[(size_t)N_NODES * 256];
__device__ __nv_bfloat16 g_Xhl[(size_t)N_NODES * 256];
__device__ __nv_bfloat16 g_Whi[(size_t)67 * CC];
__device__ __nv_bfloat16 g_Wlo[(size_t)67 * CC];

#define OFF_IN2   0
#define OFF_SEG2  (1 * CC)
#define OFF_META  (2 * CC)
#define OFF_PS    (3 * CC)
#define OFF_LR    (51 * CC)
#define OFF_CTR   (59 * CC)
#define OFF_CTR2  (63 * CC)

// ---- helpers ----
__device__ __forceinline__ u32 cvta_sm(const void* p) {
    u32 a;
    asm("{ .reg .u64 t; cvta.to.shared.u64 t, %1; cvt.u32.u64 %0, t; }" : "=r"(a) : "l"(p));
    return a;
}
__device__ __forceinline__ void red4(float* p, float a, float b, float c, float d) {
    asm volatile("red.global.add.v4.f32 [%0], {%1,%2,%3,%4};"
                 :: "l"(p), "f"(a), "f"(b), "f"(c), "f"(d) : "memory");
}
__device__ __forceinline__ u32 pack_bf2(float a, float b) {
    __nv_bfloat162 t = __floats2bfloat162_rn(a, b);
    return *(u32*)&t;
}
__device__ __forceinline__ void ldm4(u32* r, u32 addr) {
    asm volatile("ldmatrix.sync.aligned.m8n8.x4.shared.b16 {%0,%1,%2,%3}, [%4];"
                 : "=r"(r[0]), "=r"(r[1]), "=r"(r[2]), "=r"(r[3]) : "r"(addr));
}
__device__ __forceinline__ void mma_bf16(float* c, const u32* a, const u32* b) {
    asm volatile(
        "mma.sync.aligned.m16n8k16.row.col.f32.bf16.bf16.f32 "
        "{%0,%1,%2,%3}, {%4,%5,%6,%7}, {%8,%9}, {%0,%1,%2,%3};"
        : "+f"(c[0]), "+f"(c[1]), "+f"(c[2]), "+f"(c[3])
        : "r"(a[0]), "r"(a[1]), "r"(a[2]), "r"(a[3]), "r"(b[0]), "r"(b[1]));
}
__device__ __forceinline__ void cpa16(u32 dst, const void* src, u32 sz) {
    asm volatile("cp.async.cg.shared.global [%0], [%1], 16, %2;"
                 :: "r"(dst), "l"(src), "r"(sz) : "memory");
}
#define CP_COMMIT() asm volatile("cp.async.commit_group;" ::: "memory")

__device__ __forceinline__ u32 swz(int r, int c) {
    return (u32)r * 64u + (u32)((c ^ ((r >> 1) & 3)) << 4);
}

#define MMAS(A, B) do {                                                        \
    _Pragma("unroll") for (int mi_ = 0; mi_ < 2; mi_++)                        \
        _Pragma("unroll") for (int ni_ = 0; ni_ < 4; ni_++) {                  \
            mma_bf16(acc[mi_][2 * ni_],     (A)[mi_], &(B)[ni_][0]);           \
            mma_bf16(acc[mi_][2 * ni_ + 1], (A)[mi_], &(B)[ni_][2]);           \
        }                                                                      \
} while (0)

#define MMAS1(P, A, B) do {                                                    \
    _Pragma("unroll") for (int ni_ = 0; ni_ < 4; ni_++) {                      \
        mma_bf16((P)[2 * ni_],     (A), &(B)[ni_][0]);                         \
        mma_bf16((P)[2 * ni_ + 1], (A), &(B)[ni_][2]);                         \
    }                                                                          \
} while (0)

#define MTB   8192
#define OFF_AH 0
#define OFF_AL (1 * MTB)
#define OFF_BH (2 * MTB)
#define OFF_BL (3 * MTB)
#define QSET  (4 * MTB)
#define SM_IDX (3 * QSET)
#define DSM   (SM_IDX + 1024)
#define LDC   132

__device__ __forceinline__ void store_split(
    __nv_bfloat16* fo, int row, int lane, float v0, float v1, float v2, float v3)
{
    __nv_bfloat16 h0 = __float2bfloat16(v0), h1 = __float2bfloat16(v1);
    __nv_bfloat16 h2 = __float2bfloat16(v2), h3 = __float2bfloat16(v3);
    __nv_bfloat162 hh0; hh0.x = h0; hh0.y = h1;
    __nv_bfloat162 hh1; hh1.x = h2; hh1.y = h3;
    uint2 H; H.x = *(u32*)&hh0; H.y = *(u32*)&hh1;
    uint2 L;
    L.x = pack_bf2(v0 - __bfloat162float(h0), v1 - __bfloat162float(h1));
    L.y = pack_bf2(v2 - __bfloat162float(h2), v3 - __bfloat162float(h3));
    char* base = (char*)fo + (size_t)row * 512 + lane * 8;
    *(uint2*)base = H;
    *(uint2*)(base + 256) = L;
}

__device__ __forceinline__ void load_hl(
    const __nv_bfloat16* fi, int row, int lane,
    float& r0, float& r1, float& r2, float& r3)
{
    const char* base = (const char*)fi + (size_t)row * 512 + lane * 8;
    uint2 H = *(const uint2*)base;
    uint2 L = *(const uint2*)(base + 256);
    __nv_bfloat162 h0 = *(__nv_bfloat162*)&H.x;
    __nv_bfloat162 h1 = *(__nv_bfloat162*)&H.y;
    __nv_bfloat162 l0 = *(__nv_bfloat162*)&L.x;
    __nv_bfloat162 l1 = *(__nv_bfloat162*)&L.y;
    r0 = __bfloat162float(h0.x) + __bfloat162float(l0.x);
    r1 = __bfloat162float(h0.y) + __bfloat162float(l0.y);
    r2 = __bfloat162float(h1.x) + __bfloat162float(l1.x);
    r3 = __bfloat162float(h1.y) + __bfloat162float(l1.y);
}

__device__ __forceinline__ float4 gn_row(float4 v, float4 g, float4 b) {
    float s1 = v.x + v.y + v.z + v.w;
    float s2 = v.x * v.x + v.y * v.y + v.z * v.z + v.w * v.w;
    #pragma unroll
    for (int o = 16; o >= 1; o >>= 1) {
        s1 += __shfl_xor_sync(0xffffffffu, s1, o);
        s2 += __shfl_xor_sync(0xffffffffu, s2, o);
    }
    float mu = s1 * (1.f / 128.f);
    float var = s2 * (1.f / 128.f) - mu * mu;
    float rs = rsqrtf(var + 1e-5f);
    return make_float4((v.x - mu) * rs * g.x + b.x, (v.y - mu) * rs * g.y + b.y,
                       (v.z - mu) * rs * g.z + b.z, (v.w - mu) * rs * g.w + b.w);
}

// ================= dense bf16x3 GEMM =================
__device__ __forceinline__ void stage_q_d(
    u32 smb, int q, int bi, int tid, int row0, int nrows,
    const __nv_bfloat16* Ahl,
    const __nv_bfloat16* WH, const __nv_bfloat16* WL)
{
    u32 bbase = smb + (u32)bi * QSET;
    #pragma unroll
    for (int j = 0; j < 2; j++) {
        int id = tid + j * 256;
        int r = id >> 2, sg = id & 3;
        u32 doff = swz(r, sg);
        u32 asz = 16;
        int gr = row0 + r;
        if (gr >= nrows) { asz = 0; gr = 0; }
        size_t abyte = (size_t)gr * 512 + (size_t)q * 64 + (size_t)sg * 16;
        cpa16(bbase + OFF_AH + doff, (const char*)Ahl + abyte, asz);
        cpa16(bbase + OFF_AL + doff, (const char*)Ahl + abyte + 256, asz);
        size_t wbyte = (size_t)r * 256 + (size_t)q * 64 + (size_t)sg * 16;
        cpa16(bbase + OFF_BH + doff, (const char*)WH + wbyte, 16);
        cpa16(bbase + OFF_BL + doff, (const char*)WL + wbyte, 16);
    }
    CP_COMMIT();
}

// EPI: 0 fp32 store (shuffle, no smem C-tile) | 3 extras + GN + relu + split (meta)
template<int EPI>
__global__ __launch_bounds__(256, 2) void hmma_gemm(
    const __nv_bfloat16* __restrict__ Ahl,
    const __nv_bfloat16* __restrict__ Whi, const __nv_bfloat16* __restrict__ Wlo,
    float* __restrict__ out,
    const float* __restrict__ gng, const float* __restrict__ gnb,
    __nv_bfloat16* __restrict__ fo,
    int nrows,
    const float* __restrict__ turn, const float* __restrict__ control,
    const float* __restrict__ inter, const float* __restrict__ wext)
{
    extern __shared__ char dsm[];
    const int tid = threadIdx.x;
    const int wid = tid >> 5;
    const int lane = tid & 31;
    const int row0 = blockIdx.x * 128;
    const u32 smb = cvta_sm(dsm);

    const int wm = (wid & 3) * 32;
    const int wn = (wid >> 2) * 64;

    float acc[2][8][4];
    #pragma unroll
    for (int mi = 0; mi < 2; mi++)
        #pragma unroll
        for (int nj = 0; nj < 8; nj++)
            #pragma unroll
            for (int q = 0; q < 4; q++) acc[mi][nj][q] = 0.f;

    const int ra = wm + (lane & 15);
    const u32 xa = (u32)((ra >> 1) & 3);
    const int ca = lane >> 4;
    const int rb = wn + (lane & 7) + ((lane >> 4) & 1) * 8;
    const u32 xb = (u32)((rb >> 1) & 3);
    const int cb = (lane >> 3) & 1;

    stage_q_d(smb, 0, 0, tid, row0, nrows, Ahl, Whi, Wlo);
    stage_q_d(smb, 1, 1, tid, row0, nrows, Ahl, Whi, Wlo);
    stage_q_d(smb, 2, 2, tid, row0, nrows, Ahl, Whi, Wlo);

    #pragma unroll
    for (int q = 0; q < 4; q++) {
        if (q <= 1)      asm volatile("cp.async.wait_group 2;" ::: "memory");
        else if (q == 2) asm volatile("cp.async.wait_group 1;" ::: "memory");
        else             asm volatile("cp.async.wait_group 0;" ::: "memory");
        __syncthreads();

        const u32 qb = smb + (u32)(q % 3) * QSET;
        #pragma unroll
        for (int ks = 0; ks < 2; ks++) {
            const u32 ach = (u32)(ks * 2 + ca) ^ xa;
            const u32 bch = (u32)(ks * 2 + cb) ^ xb;
            const u32 aoff = (u32)ra * 64u + (ach << 4);
            u32 a0[2][4], a1[2][4], b0[4][4], b1[4][4];
            ldm4(a0[0], qb + OFF_AH + aoff);
            ldm4(a0[1], qb + OFF_AH + aoff + 16 * 64);
            #pragma unroll
            for (int ni = 0; ni < 4; ni++)
                ldm4(b0[ni], qb + OFF_BH + (u32)(rb + ni * 16) * 64u + (bch << 4));
            MMAS(a0, b0);
            ldm4(a1[0], qb + OFF_AL + aoff);
            ldm4(a1[1], qb + OFF_AL + aoff + 16 * 64);
            MMAS(a1, b0);
            #pragma unroll
            for (int ni = 0; ni < 4; ni++)
                ldm4(b1[ni], qb + OFF_BL + (u32)(rb + ni * 16) * 64u + (bch << 4));
            MMAS(a0, b1);
        }

        if (q == 0) {
            __syncthreads();
            stage_q_d(smb, 3, 0, tid, row0, nrows, Ahl, Whi, Wlo);
        }
    }

    if (EPI == 0) {
        // direct fragment -> STG via pair shuffle (no smem C-tile, no syncs)
        #pragma unroll
        for (int mi = 0; mi < 2; mi++) {
            int r_e = row0 + wm + mi * 16 + (lane >> 2);
            int r_o = r_e + 8;
            int cbx = wn + ((lane >> 1) & 1) * 4;
            #pragma unroll
            for (int nj = 0; nj < 8; nj++) {
                float x0 = acc[mi][nj][0], x1 = acc[mi][nj][1];
                float y0 = acc[mi][nj][2], y1 = acc[mi][nj][3];
                float px0 = __shfl_xor_sync(0xffffffffu, x0, 1);
                float px1 = __shfl_xor_sync(0xffffffffu, x1, 1);
                float py0 = __shfl_xor_sync(0xffffffffu, y0, 1);
                float py1 = __shfl_xor_sync(0xffffffffu, y1, 1);
                int cc = cbx + nj * 8;
                if ((lane & 1) == 0) {
                    if (r_e < nrows)
                        *(float4*)(out + (size_t)r_e * C + cc) =
                            make_float4(x0, x1, px0, px1);
                } else {
                    if (r_o < nrows)
                        *(float4*)(out + (size_t)r_o * C + cc) =
                            make_float4(py0, py1, y0, y1);
                }
            }
        }
        return;
    }

    // ---- EPI 3: smem C-tile + row-wise epilogue ----
    __syncthreads();
    float* Csm = (float*)dsm;
    #pragma unroll
    for (int mi = 0; mi < 2; mi++)
        #pragma unroll
        for (int nj = 0; nj < 8; nj++) {
            int r = wm + mi * 16 + (lane >> 2);
            int c = wn + nj * 8 + (lane & 3) * 2;
            float* p = Csm + (size_t)r * LDC + c;
            p[0] = acc[mi][nj][0];
            p[1] = acc[mi][nj][1];
            p[8 * LDC] = acc[mi][nj][2];
            p[8 * LDC + 1] = acc[mi][nj][3];
        }
    __syncthreads();

    float4 gv = *(const float4*)(gng + lane * 4);
    float4 bv = *(const float4*)(gnb + lane * 4);
    float4 we[4];
    #pragma unroll
    for (int j = 0; j < 4; j++)
        we[j] = *(const float4*)(wext + (size_t)j * C + lane * 4);

    for (int i = 0; i < 16; i++) {
        int r = wid * 16 + i;
        int row = row0 + r;
        if (row >= nrows) continue;
        float4 v = *(float4*)(Csm + (size_t)r * LDC + lane * 4);
        float t0 = turn[2 * row], t1 = turn[2 * row + 1];
        float cc0 = control[row], it = inter[row];
        v.x += t0 * we[0].x + t1 * we[1].x + cc0 * we[2].x + it * we[3].x;
        v.y += t0 * we[0].y + t1 * we[1].y + cc0 * we[2].y + it * we[3].y;
        v.z += t0 * we[0].z + t1 * we[1].z + cc0 * we[2].z + it * we[3].z;
        v.w += t0 * we[0].w + t1 * we[1].w + cc0 * we[2].w + it * we[3].w;
        float4 o = gn_row(v, gv, bv);
        store_split(fo, row, lane, fmaxf(o.x, 0.f), fmaxf(o.y, 0.f),
                    fmaxf(o.z, 0.f), fmaxf(o.w, 0.f));
    }
}

// ============ edge GEMM: all pre/suc/left/right in one launch, RED into T ========
__global__ __launch_bounds__(256, 2) void edge_gemm(
    const __nv_bfloat16* __restrict__ Ahl,
    const __nv_bfloat16* __restrict__ Whi, const __nv_bfloat16* __restrict__ Wlo,
    float* __restrict__ T,
    const int* __restrict__ pre, const int* __restrict__ suc,
    const int* __restrict__ left, const int* __restrict__ right,
    int layer)
{
    const int y = blockIdx.y;
    const int* dbase;
    int nedges;
    size_t wslot;
    if (y < 6) {
        dbase = pre + (size_t)y * 2 * EP; nedges = EP;
        wslot = OFF_PS + (size_t)(layer * 12 + y) * CC;
    } else if (y < 12) {
        dbase = suc + (size_t)(y - 6) * 2 * EP; nedges = EP;
        wslot = OFF_PS + (size_t)(layer * 12 + y) * CC;
    } else {
        if (blockIdx.x >= 196) return;
        dbase = (y == 12) ? left : right; nedges = EL;
        wslot = OFF_LR + (size_t)(layer * 2 + (y - 12)) * CC;
    }
    const int* sbase = dbase + nedges;

    extern __shared__ char dsm[];
    const int tid = threadIdx.x;
    const int wid = tid >> 5;
    const int lane = tid & 31;
    const u32 smb = cvta_sm(dsm);
    int* s_dst = (int*)(dsm + SM_IDX);
    int* s_src = s_dst + 128;

    const __nv_bfloat16* WH = Whi + wslot;
    const __nv_bfloat16* WL = Wlo + wslot;

    if (tid < 128) {
        int e = blockIdx.x * 128 + tid;
        s_dst[tid] = (e < nedges) ? dbase[e] : -1;
        s_src[tid] = (e < nedges) ? sbase[e] : 0;
    }
    __syncthreads();

    const int wm = (wid & 3) * 32;
    const int wn = (wid >> 2) * 64;

    float acc[2][8][4];
    #pragma unroll
    for (int mi = 0; mi < 2; mi++)
        #pragma unroll
        for (int nj = 0; nj < 8; nj++)
            #pragma unroll
            for (int q = 0; q < 4; q++) acc[mi][nj][q] = 0.f;

    const int ra = wm + (lane & 15);
    const u32 xa = (u32)((ra >> 1) & 3);
    const int ca = lane >> 4;
    const int rb = wn + (lane & 7) + ((lane >> 4) & 1) * 8;
    const u32 xb = (u32)((rb >> 1) & 3);
    const int cb = (lane >> 3) & 1;

    #define STAGE_QG(qq, bi) do {                                              \
        u32 bbase_ = smb + (u32)(bi) * QSET;                                   \
        _Pragma("unroll") for (int j = 0; j < 2; j++) {                        \
            int id = tid + j * 256;                                            \
            int r = id >> 2, sg = id & 3;                                      \
            u32 doff = swz(r, sg);                                             \
            size_t abyte = (size_t)s_src[r] * 512 + (size_t)(qq) * 64 + (size_t)sg * 16; \
            cpa16(bbase_ + OFF_AH + doff, (const char*)Ahl + abyte, 16);       \
            cpa16(bbase_ + OFF_AL + doff, (const char*)Ahl + abyte + 256, 16); \
            size_t wbyte = (size_t)r * 256 + (size_t)(qq) * 64 + (size_t)sg * 16; \
            cpa16(bbase_ + OFF_BH + doff, (const char*)WH + wbyte, 16);        \
            cpa16(bbase_ + OFF_BL + doff, (const char*)WL + wbyte, 16);        \
        }                                                                      \
        CP_COMMIT();                                                           \
    } while (0)

    STAGE_QG(0, 0);
    STAGE_QG(1, 1);
    STAGE_QG(2, 2);

    #pragma unroll
    for (int q = 0; q < 4; q++) {
        if (q <= 1)      asm volatile("cp.async.wait_group 2;" ::: "memory");
        else if (q == 2) asm volatile("cp.async.wait_group 1;" ::: "memory");
        else             asm volatile("cp.async.wait_group 0;" ::: "memory");
        __syncthreads();

        const u32 qb = smb + (u32)(q % 3) * QSET;
        #pragma unroll
        for (int ks = 0; ks < 2; ks++) {
            const u32 ach = (u32)(ks * 2 + ca) ^ xa;
            const u32 bch = (u32)(ks * 2 + cb) ^ xb;
            const u32 aoff = (u32)ra * 64u + (ach << 4);
            u32 a0[2][4], a1[2][4], b0[4][4], b1[4][4];
            ldm4(a0[0], qb + OFF_AH + aoff);
            ldm4(a0[1], qb + OFF_AH + aoff + 16 * 64);
            #pragma unroll
            for (int ni = 0; ni < 4; ni++)
                ldm4(b0[ni], qb + OFF_BH + (u32)(rb + ni * 16) * 64u + (bch << 4));
            MMAS(a0, b0);
            ldm4(a1[0], qb + OFF_AL + aoff);
            ldm4(a1[1], qb + OFF_AL + aoff + 16 * 64);
            MMAS(a1, b0);
            #pragma unroll
            for (int ni = 0; ni < 4; ni++)
                ldm4(b1[ni], qb + OFF_BL + (u32)(rb + ni * 16) * 64u + (bch << 4));
            MMAS(a0, b1);
        }

        if (q == 0) {
            __syncthreads();
            STAGE_QG(3, 0);
        }
    }
    #undef STAGE_QG

    // direct fragment -> RED via pair shuffle (no smem C-tile, no syncs)
    #pragma unroll
    for (int mi = 0; mi < 2; mi++) {
        int rbase = wm + mi * 16 + (lane >> 2);
        int dd_e = s_dst[rbase];
        int dd_o = s_dst[rbase + 8];
        int cbx = wn + ((lane >> 1) & 1) * 4;
        #pragma unroll
        for (int nj = 0; nj < 8; nj++) {
            float x0 = acc[mi][nj][0], x1 = acc[mi][nj][1];
            float y0 = acc[mi][nj][2], y1 = acc[mi][nj][3];
            float px0 = __shfl_xor_sync(0xffffffffu, x0, 1);
            float px1 = __shfl_xor_sync(0xffffffffu, x1, 1);
            float py0 = __shfl_xor_sync(0xffffffffu, y0, 1);
            float py1 = __shfl_xor_sync(0xffffffffu, y1, 1);
            int cc = cbx + nj * 8;
            if ((lane & 1) == 0) {
                if (dd_e >= 0)
                    red4(T + (size_t)dd_e * C + cc, x0, x1, px0, px1);
            } else {
                if (dd_o >= 0)
                    red4(T + (size_t)dd_o * C + cc, py0, py1, y0, y1);
            }
        }
    }
}

// ======== gn_gemm: A = relu(gn(T)) in-kernel, C = A @ W, residual from bf16 hi/lo ==
#define G_AH   0
#define G_AL   32768
#define G_B    65536
#define G_DSM  98304

__global__ __launch_bounds__(256, 2) void gn_gemm(
    const float* __restrict__ Tg,
    const float* __restrict__ ing, const float* __restrict__ inb,
    const __nv_bfloat16* __restrict__ Whi, const __nv_bfloat16* __restrict__ Wlo,
    float* __restrict__ wout,
    const float* __restrict__ outg, const float* __restrict__ outb,
    const __nv_bfloat16* __restrict__ addhl,
    __nv_bfloat16* __restrict__ fo,
    int nrows)
{
    extern __shared__ char dsm[];
    const int tid = threadIdx.x;
    const int wid = tid >> 5;
    const int lane = tid & 31;
    const int row0 = blockIdx.x * 128;
    const u32 smb = cvta_sm(dsm);

    #define STAGE_B2(qq, bi) do {                                              \
        u32 bb_ = smb + G_B + (u32)(bi) * 16384u;                              \
        _Pragma("unroll") for (int j = 0; j < 2; j++) {                        \
            int id = tid + j * 256;                                            \
            int r = id >> 2, sg = id & 3;                                      \
            u32 doff = swz(r, sg);                                             \
            size_t wbyte = (size_t)r * 256 + (size_t)(qq) * 64 + (size_t)sg * 16; \
            cpa16(bb_ + doff, (const char*)Whi + wbyte, 16);                   \
            cpa16(bb_ + 8192u + doff, (const char*)Wlo + wbyte, 16);           \
        }                                                                      \
        CP_COMMIT();                                                           \
    } while (0)

    STAGE_B2(0, 0);
    STAGE_B2(1, 1);

    {
        float4 gin = *(const float4*)(ing + lane * 4);
        float4 bin = *(const float4*)(inb + lane * 4);
        const int q  = lane >> 3;
        const int c  = (lane >> 1) & 3;
        const int o8 = (lane & 1) * 8;
        #pragma unroll 4
        for (int it = 0; it < 16; it++) {
            int r = wid + it * 8;
            int row = row0 + r;
            float4 v = make_float4(0.f, 0.f, 0.f, 0.f);
            if (row < nrows) v = *(const float4*)(Tg + (size_t)row * C + lane * 4);
            float4 o = gn_row(v, gin, bin);
            float v0 = fmaxf(o.x, 0.f), v1 = fmaxf(o.y, 0.f);
            float v2 = fmaxf(o.z, 0.f), v3 = fmaxf(o.w, 0.f);
            __nv_bfloat16 h0 = __float2bfloat16(v0), h1 = __float2bfloat16(v1);
            __nv_bfloat16 h2 = __float2bfloat16(v2), h3 = __float2bfloat16(v3);
            __nv_bfloat162 hh0; hh0.x = h0; hh0.y = h1;
            __nv_bfloat162 hh1; hh1.x = h2; hh1.y = h3;
            uint2 H; H.x = *(u32*)&hh0; H.y = *(u32*)&hh1;
            uint2 L;
            L.x = pack_bf2(v0 - __bfloat162float(h0), v1 - __bfloat162float(h1));
            L.y = pack_bf2(v2 - __bfloat162float(h2), v3 - __bfloat162float(h3));
            u32 off = (u32)q * 8192u + swz(r, c) + (u32)o8;
            *(uint2*)(dsm + G_AH + off) = H;
            *(uint2*)(dsm + G_AL + off) = L;
        }
    }

    const int wm = (wid & 3) * 32;
    const int wn = (wid >> 2) * 64;

    float acc[2][8][4];
    #pragma unroll
    for (int mi = 0; mi < 2; mi++)
        #pragma unroll
        for (int nj = 0; nj < 8; nj++)
            #pragma unroll
            for (int q = 0; q < 4; q++) acc[mi][nj][q] = 0.f;

    const int ra = wm + (lane & 15);
    const u32 xa = (u32)((ra >> 1) & 3);
    const int ca = lane >> 4;
    const int rb = wn + (lane & 7) + ((lane >> 4) & 1) * 8;
    const u32 xb = (u32)((rb >> 1) & 3);
    const int cb = (lane >> 3) & 1;

    #pragma unroll
    for (int q = 0; q < 4; q++) {
        if (q < 3) asm volatile("cp.async.wait_group 1;" ::: "memory");
        else       asm volatile("cp.async.wait_group 0;" ::: "memory");
        __syncthreads();

        const u32 aqh = smb + G_AH + (u32)q * 8192u;
        const u32 aql = smb + G_AL + (u32)q * 8192u;
        const u32 bqh = smb + G_B + (u32)(q & 1) * 16384u;
        const u32 bql = bqh + 8192u;
        #pragma unroll
        for (int ks = 0; ks < 2; ks++) {
            const u32 ach = (u32)(ks * 2 + ca) ^ xa;
            const u32 bch = (u32)(ks * 2 + cb) ^ xb;
            const u32 aoff = (u32)ra * 64u + (ach << 4);
            u32 a0[2][4], a1[2][4], b0[4][4], b1[4][4];
            ldm4(a0[0], aqh + aoff);
            ldm4(a0[1], aqh + aoff + 16 * 64);
            #pragma unroll
            for (int ni = 0; ni < 4; ni++)
                ldm4(b0[ni], bqh + (u32)(rb + ni * 16) * 64u + (bch << 4));
            MMAS(a0, b0);
            ldm4(a1[0], aql + aoff);
            ldm4(a1[1], aql + aoff + 16 * 64);
            MMAS(a1, b0);
            #pragma unroll
            for (int ni = 0; ni < 4; ni++)
                ldm4(b1[ni], bql + (u32)(rb + ni * 16) * 64u + (bch << 4));
            MMAS(a0, b1);
        }

        if (q < 2) {
            __syncthreads();
            STAGE_B2(q + 2, q & 1);
        }
    }
    #undef STAGE_B2

    __syncthreads();
    float* Csm = (float*)dsm;
    #pragma unroll
    for (int mi = 0; mi < 2; mi++)
        #pragma unroll
        for (int nj = 0; nj < 8; nj++) {
            int r = wm + mi * 16 + (lane >> 2);
            int c = wn + nj * 8 + (lane & 3) * 2;
            float* p = Csm + (size_t)r * LDC + c;
            p[0] = acc[mi][nj][0];
            p[1] = acc[mi][nj][1];
            p[8 * LDC] = acc[mi][nj][2];
            p[8 * LDC + 1] = acc[mi][nj][3];
        }
    __syncthreads();

    float4 gv = *(const float4*)(outg + lane * 4);
    float4 bv = *(const float4*)(outb + lane * 4);

    for (int i = 0; i < 16; i++) {
        int r = wid * 16 + i;
        int row = row0 + r;
        if (row >= nrows) continue;
        float4 v = *(float4*)(Csm + (size_t)r * LDC + lane * 4);
        float4 o = gn_row(v, gv, bv);
        float r0, r1, r2, r3;
        load_hl(addhl, row, lane, r0, r1, r2, r3);
        float v0 = fmaxf(o.x + r0, 0.f);
        float v1 = fmaxf(o.y + r1, 0.f);
        float v2 = fmaxf(o.z + r2, 0.f);
        float v3 = fmaxf(o.w + r3, 0.f);
        if (wout)
            *(float4*)(wout + (size_t)row * C + lane * 4) = make_float4(v0, v1, v2, v3);
        store_split(fo, row, lane, v0, v1, v2, v3);
    }
}

// ======== dual_gemm: fused prologue in2+seg2 =========================
#define D_QA  0
#define D_QB  16384
#define D_QSET 49152
#define D_DSM  98304
#define LDC64  132

__global__ __launch_bounds__(256, 2) void dual_gemm(
    const __nv_bfloat16* __restrict__ H1, const __nv_bfloat16* __restrict__ H2,
    const __nv_bfloat16* __restrict__ Whi, const __nv_bfloat16* __restrict__ Wlo,
    const float* __restrict__ g1, const float* __restrict__ b1,
    const float* __restrict__ g2, const float* __restrict__ b2,
    __nv_bfloat16* __restrict__ fo, int nrows)
{
    extern __shared__ char dsm[];
    const int tid = threadIdx.x;
    const int wid = tid >> 5;
    const int lane = tid & 31;
    const int row0 = blockIdx.x * 64;
    const u32 smb = cvta_sm(dsm);

    const __nv_bfloat16* W1h = Whi + OFF_IN2;
    const __nv_bfloat16* W1l = Wlo + OFF_IN2;
    const __nv_bfloat16* W2h = Whi + OFF_SEG2;
    const __nv_bfloat16* W2l = Wlo + OFF_SEG2;

    #define STAGE_D(qq, bi) do {                                               \
        u32 qa_ = smb + (u32)(bi) * D_QSET + D_QA;                             \
        u32 qb_ = smb + (u32)(bi) * D_QSET + D_QB;                             \
        {                                                                      \
            int r = tid >> 2, sg = tid & 3;                                    \
            u32 doff = swz(r, sg);                                             \
            u32 asz = 16;                                                      \
            int gr = row0 + r;                                                 \
            if (gr >= nrows) { asz = 0; gr = 0; }                              \
            size_t ab = (size_t)gr * 512 + (size_t)(qq) * 64 + (size_t)sg * 16; \
            cpa16(qa_ + 0u     + doff, (const char*)H1 + ab, asz);             \
            cpa16(qa_ + 4096u  + doff, (const char*)H1 + ab + 256, asz);       \
            cpa16(qa_ + 8192u  + doff, (const char*)H2 + ab, asz);             \
            cpa16(qa_ + 12288u + doff, (const char*)H2 + ab + 256, asz);       \
        }                                                                      \
        _Pragma("unroll") for (int j = 0; j < 2; j++) {                        \
            int id = tid + j * 256;                                            \
            int r = id >> 2, sg = id & 3;                                      \
            u32 doff = swz(r, sg);                                             \
            size_t wb = (size_t)r * 256 + (size_t)(qq) * 64 + (size_t)sg * 16; \
            cpa16(qb_ + 0u      + doff, (const char*)W1h + wb, 16);            \
            cpa16(qb_ + 8192u   + doff, (const char*)W1l + wb, 16);            \
            cpa16(qb_ + 16384u  + doff, (const char*)W2h + wb, 16);            \
            cpa16(qb_ + 24576u  + doff, (const char*)W2l + wb, 16);            \
        }                                                                      \
        CP_COMMIT();                                                           \
    } while (0)

    STAGE_D(0, 0);
    STAGE_D(1, 1);

    const int wm = (wid & 3) * 16;
    const int wn = (wid >> 2) * 64;

    float accP[8][4], accQ[8][4];
    #pragma unroll
    for (int nj = 0; nj < 8; nj++)
        #pragma unroll
        for (int q = 0; q < 4; q++) { accP[nj][q] = 0.f; accQ[nj][q] = 0.f; }

    const int ra = wm + (lane & 15);
    const u32 xa = (u32)((ra >> 1) & 3);
    const int ca = lane >> 4;
    const int rb = wn + (lane & 7) + ((lane >> 4) & 1) * 8;
    const u32 xb = (u32)((rb >> 1) & 3);
    const int cb = (lane >> 3) & 1;

    #pragma unroll
    for (int q = 0; q < 4; q++) {
        if (q < 3) asm volatile("cp.async.wait_group 1;" ::: "memory");
        else       asm volatile("cp.async.wait_group 0;" ::: "memory");
        __syncthreads();

        const u32 qa = smb + (u32)(q & 1) * D_QSET + D_QA;
        const u32 qb = smb + (u32)(q & 1) * D_QSET + D_QB;
        #pragma unroll
        for (int ks = 0; ks < 2; ks++) {
            const u32 ach = (u32)(ks * 2 + ca) ^ xa;
            const u32 bch = (u32)(ks * 2 + cb) ^ xb;
            const u32 aoff = (u32)ra * 64u + (ach << 4);
            u32 a0[4], a1[4], b0[4][4], b1[4][4];
            ldm4(a0, qa + aoff);
            #pragma unroll
            for (int ni = 0; ni < 4; ni++)
                ldm4(b0[ni], qb + (u32)(rb + ni * 16) * 64u + (bch << 4));
            MMAS1(accP, a0, b0);
            ldm4(a1, qa + 4096u + aoff);
            MMAS1(accP, a1, b0);
            #pragma unroll
            for (int ni = 0; ni < 4; ni++)
                ldm4(b1[ni], qb + 8192u + (u32)(rb + ni * 16) * 64u + (bch << 4));
            MMAS1(accP, a0, b1);
            ldm4(a0, qa + 8192u + aoff);
            #pragma unroll
            for (int ni = 0; ni < 4; ni++)
                ldm4(b0[ni], qb + 16384u + (u32)(rb + ni * 16) * 64u + (bch << 4));
            MMAS1(accQ, a0, b0);
            ldm4(a1, qa + 12288u + aoff);
            MMAS1(accQ, a1, b0);
            #pragma unroll
            for (int ni = 0; ni < 4; ni++)
                ldm4(b1[ni], qb + 24576u + (u32)(rb + ni * 16) * 64u + (bch << 4));
            MMAS1(accQ, a0, b1);
        }

        if (q < 2) {
            __syncthreads();
            STAGE_D(q + 2, q & 1);
        }
    }
    #undef STAGE_D

    __syncthreads();
    float* CsmP = (float*)dsm;
    float* CsmQ = (float*)(dsm + 64 * LDC64 * 4);
    #pragma unroll
    for (int nj = 0; nj < 8; nj++) {
        int r = wm + (lane >> 2);
        int c = wn + nj * 8 + (lane & 3) * 2;
        float* p = CsmP + (size_t)r * LDC64 + c;
        p[0] = accP[nj][0]; p[1] = accP[nj][1];
        p[8 * LDC64] = accP[nj][2]; p[8 * LDC64 + 1] = accP[nj][3];
        float* qp = CsmQ + (size_t)r * LDC64 + c;
        qp[0] = accQ[nj][0]; qp[1] = accQ[nj][1];
        qp[8 * LDC64] = accQ[nj][2]; qp[8 * LDC64 + 1] = accQ[nj][3];
    }
    __syncthreads();

    float4 g1v = *(const float4*)(g1 + lane * 4);
    float4 b1v = *(const float4*)(b1 + lane * 4);
    float4 g2v = *(const float4*)(g2 + lane * 4);
    float4 b2v = *(const float4*)(b2 + lane * 4);

    for (int i = 0; i < 8; i++) {
        int r = wid * 8 + i;
        int row = row0 + r;
        if (row >= nrows) continue;
        float4 vp = *(float4*)(CsmP + (size_t)r * LDC64 + lane * 4);
        float4 vq = *(float4*)(CsmQ + (size_t)r * LDC64 + lane * 4);
        float4 a = gn_row(vp, g1v, b1v);
        float4 b = gn_row(vq, g2v, b2v);
        store_split(fo, row, lane,
                    fmaxf(a.x + b.x, 0.f), fmaxf(a.y + b.y, 0.f),
                    fmaxf(a.z + b.z, 0.f), fmaxf(a.w + b.w, 0.f));
    }
}

// ================= fused prep kernel =================
#define PREP_COPY_B 1563
#define PREP_W_B    4288
#define PREP_IN_B   25000

__global__ void prep(
    const float* __restrict__ ctrs, const float* __restrict__ feats,
    const float* __restrict__ w_in1, const float* __restrict__ b_in1,
    const float* __restrict__ w_seg1, const float* __restrict__ b_seg1,
    const float* __restrict__ w_in2, const float* __restrict__ w_seg2,
    const float* __restrict__ w_meta,
    const float* __restrict__ ctr_w, const float* __restrict__ pre_w,
    const float* __restrict__ suc_w, const float* __restrict__ left_w,
    const float* __restrict__ right_w, const float* __restrict__ ctr2_w,
    __nv_bfloat16* __restrict__ whi, __nv_bfloat16* __restrict__ wlo,
    __nv_bfloat16* __restrict__ h1, __nv_bfloat16* __restrict__ h2,
    float* __restrict__ out_tail)
{
    int b = blockIdx.x;
    int tid = threadIdx.x;
    if (b < PREP_COPY_B) {
        int i = b * 256 + tid;
        if (i < N_NODES * 2) out_tail[i] = ctrs[i];
        return;
    }
    b -= PREP_COPY_B;
    if (b < PREP_W_B) {
        int idx = b * 256 + tid;
        int mat = idx >> 14;
        int rem = idx & 16383;
        int k = rem >> 7, n = rem & 127;
        const float* src;
        if      (mat == 0) src = w_in2 + rem;
        else if (mat == 1) src = w_seg2 + rem;
        else if (mat == 2) src = w_meta + rem;
        else if (mat < 51) {
            int m = mat - 3; int i = m / 12; int r = m % 12;
            src = (r < 6) ? pre_w + (size_t)(i * 6 + r) * CC + rem
                          : suc_w + (size_t)(i * 6 + r - 6) * CC + rem;
        } else if (mat < 59) {
            int m = mat - 51; int i = m >> 1;
            src = ((m & 1) ? right_w : left_w) + (size_t)i * CC + rem;
        } else if (mat < 63) src = ctr_w  + (size_t)(mat - 59) * CC + rem;
        else                 src = ctr2_w + (size_t)(mat - 63) * CC + rem;
        float x = *src;
        __nv_bfloat16 h = __float2bfloat16(x);
        size_t o = (size_t)mat * CC + (size_t)n * C + k;
        whi[o] = h;
        wlo[o] = __float2bfloat16(x - __bfloat162float(h));
        return;
    }
    b -= PREP_W_B;
    {
        int i = b * 256 + tid;
        int n = i >> 5, lane = i & 31;
        float x0 = ctrs[2 * n], x1 = ctrs[2 * n + 1];
        float4 wa = *(const float4*)(w_in1 + lane * 4);
        float4 wb = *(const float4*)(w_in1 + C + lane * 4);
        float4 bb = *(const float4*)(b_in1 + lane * 4);
        float a0 = fmaxf(x0 * wa.x + x1 * wb.x + bb.x, 0.f);
        float a1 = fmaxf(x0 * wa.y + x1 * wb.y + bb.y, 0.f);
        float a2 = fmaxf(x0 * wa.z + x1 * wb.z + bb.z, 0.f);
        float a3 = fmaxf(x0 * wa.w + x1 * wb.w + bb.w, 0.f);
        store_split(h1, n, lane, a0, a1, a2, a3);
        float y0 = feats[2 * n], y1 = feats[2 * n + 1];
        float4 wc = *(const float4*)(w_seg1 + lane * 4);
        float4 wd = *(const float4*)(w_seg1 + C + lane * 4);
        float4 bd = *(const float4*)(b_seg1 + lane * 4);
        float c0 = fmaxf(y0 * wc.x + y1 * wd.x + bd.x, 0.f);
        float c1 = fmaxf(y0 * wc.y + y1 * wd.y + bd.y, 0.f);
        float c2 = fmaxf(y0 * wc.z + y1 * wd.z + bd.z, 0.f);
        float c3 = fmaxf(y0 * wc.w + y1 * wd.w + bd.w, 0.f);
        store_split(h2, n, lane, c0, c1, c2, c3);
    }
}

// ================= host launcher =================
extern "C" void kernel_launch(void* const* d_in, const int* in_sizes, int n_in,
                              void* d_out, int out_size)
{
    const float* control  = (const float*)d_in[0];
    const float* turn     = (const float*)d_in[1];
    const float* inter    = (const float*)d_in[2];
    const float* ctrs     = (const float*)d_in[3];
    const float* feats    = (const float*)d_in[4];
    const int*   pre      = (const int*)d_in[5];
    const int*   suc      = (const int*)d_in[6];
    const int*   left     = (const int*)d_in[7];
    const int*   right    = (const int*)d_in[8];
    const float* w_in1    = (const float*)d_in[9];
    const float* b_in1    = (const float*)d_in[10];
    const float* w_in2    = (const float*)d_in[11];
    const float* gn_in_g  = (const float*)d_in[12];
    const float* gn_in_b  = (const float*)d_in[13];
    const float* w_seg1   = (const float*)d_in[14];
    const float* b_seg1   = (const float*)d_in[15];
    const float* w_seg2   = (const float*)d_in[16];
    const float* gn_seg_g = (const float*)d_in[17];
    const float* gn_seg_b = (const float*)d_in[18];
    const float* w_meta   = (const float*)d_in[19];
    const float* gn_m_g   = (const float*)d_in[20];
    const float* gn_m_b   = (const float*)d_in[21];
    const float* ctr_w    = (const float*)d_in[22];
    const float* pre_w    = (const float*)d_in[23];
    const float* suc_w    = (const float*)d_in[24];
    const float* left_w   = (const float*)d_in[25];
    const float* right_w  = (const float*)d_in[26];
    const float* norm_g   = (const float*)d_in[27];
    const float* norm_b   = (const float*)d_in[28];
    const float* ctr2_w   = (const float*)d_in[29];
    const float* ctr2_g   = (const float*)d_in[30];
    const float* ctr2_b   = (const float*)d_in[31];

    float* T;
    __nv_bfloat16 *Fhl, *Xhl, *Whi, *Wlo;
    cudaGetSymbolAddress((void**)&T, g_T);
    cudaGetSymbolAddress((void**)&Fhl, g_Fhl);
    cudaGetSymbolAddress((void**)&Xhl, g_Xhl);
    cudaGetSymbolAddress((void**)&Whi, g_Whi);
    cudaGetSymbolAddress((void**)&Wlo, g_Wlo);

    cudaFuncSetAttribute(hmma_gemm<0>, cudaFuncAttributeMaxDynamicSharedMemorySize, DSM);
    cudaFuncSetAttribute(hmma_gemm<3>, cudaFuncAttributeMaxDynamicSharedMemorySize, DSM);
    cudaFuncSetAttribute(edge_gemm, cudaFuncAttributeMaxDynamicSharedMemorySize, DSM);
    cudaFuncSetAttribute(gn_gemm, cudaFuncAttributeMaxDynamicSharedMemorySize, G_DSM);
    cudaFuncSetAttribute(dual_gemm, cudaFuncAttributeMaxDynamicSharedMemorySize, D_DSM);

    const int NB = (N_NODES + 127) / 128;
    const int NB64 = (N_NODES + 63) / 64;
    const int NBP = (EP + 127) / 128;   // 782
    const float* wext = w_meta + 128 * C;

    prep<<<PREP_COPY_B + PREP_W_B + PREP_IN_B, 256>>>(
        ctrs, feats, w_in1, b_in1, w_seg1, b_seg1,
        w_in2, w_seg2, w_meta, ctr_w, pre_w, suc_w, left_w, right_w, ctr2_w,
        Whi, Wlo, Xhl, Fhl, (float*)d_out + (size_t)N_NODES * C);
    dual_gemm<<<NB64, 256, D_DSM>>>(Xhl, Fhl, Whi, Wlo,
        gn_in_g, gn_in_b, gn_seg_g, gn_seg_b, Xhl, N_NODES);
    hmma_gemm<3><<<NB, 256, DSM>>>(Xhl, Whi + OFF_META, Wlo + OFF_META,
        nullptr, gn_m_g, gn_m_b, Fhl, N_NODES,
        turn, control, inter, wext);

    for (int i = 0; i < 4; i++) {
        float* wout = (i == 3) ? (float*)d_out : nullptr;

        hmma_gemm<0><<<NB, 256, DSM>>>(
            Fhl, Whi + OFF_CTR + (size_t)i * CC, Wlo + OFF_CTR + (size_t)i * CC,
            T, nullptr, nullptr, nullptr, N_NODES,
            nullptr, nullptr, nullptr, nullptr);
        edge_gemm<<<dim3(NBP, 14), 256, DSM>>>(
            Fhl, Whi, Wlo, T, pre, suc, left, right, i);
        gn_gemm<<<NB, 256, G_DSM>>>(
            T, norm_g + (size_t)i * C, norm_b + (size_t)i * C,
            Whi + OFF_CTR2 + (size_t)i * CC, Wlo + OFF_CTR2 + (size_t)i * CC,
            wout, ctr2_g + (size_t)i * C, ctr2_b + (size_t)i * C, Fhl,
            Fhl, N_NODES);
    }
}

// round 14
// speedup vs baseline: 1.0396x; 1.0396x over previous
#include <cuda_runtime.h>
#include <cuda_bf16.h>
#include <cstdint>
#include <cstddef>

#define N_NODES 200000
#define C 128
#define S 6
#define EP 100000
#define EL 25000
#define CC 16384

typedef unsigned long long u64;
typedef unsigned int u32;

// ---- static device scratch ----
__device__ float g_T[(size_t)N_NODES * C];
__device__ __nv_bfloat16 g_Fhl[(size_t)N_NODES * 256];
__device__ __nv_bfloat16 g_Xhl[(size_t)N_NODES * 256];
__device__ __nv_bfloat16 g_Whi[(size_t)67 * CC];
__device__ __nv_bfloat16 g_Wlo[(size_t)67 * CC];

#define OFF_IN2   0
#define OFF_SEG2  (1 * CC)
#define OFF_META  (2 * CC)
#define OFF_PS    (3 * CC)
#define OFF_LR    (51 * CC)
#define OFF_CTR   (59 * CC)
#define OFF_CTR2  (63 * CC)

// ---- helpers ----
__device__ __forceinline__ u32 cvta_sm(const void* p) {
    u32 a;
    asm("{ .reg .u64 t; cvta.to.shared.u64 t, %1; cvt.u32.u64 %0, t; }" : "=r"(a) : "l"(p));
    return a;
}
__device__ __forceinline__ void red4(float* p, float a, float b, float c, float d) {
    asm volatile("red.global.add.v4.f32 [%0], {%1,%2,%3,%4};"
                 :: "l"(p), "f"(a), "f"(b), "f"(c), "f"(d) : "memory");
}
__device__ __forceinline__ u32 pack_bf2(float a, float b) {
    __nv_bfloat162 t = __floats2bfloat162_rn(a, b);
    return *(u32*)&t;
}
__device__ __forceinline__ void ldm4(u32* r, u32 addr) {
    asm volatile("ldmatrix.sync.aligned.m8n8.x4.shared.b16 {%0,%1,%2,%3}, [%4];"
                 : "=r"(r[0]), "=r"(r[1]), "=r"(r[2]), "=r"(r[3]) : "r"(addr));
}
__device__ __forceinline__ void mma_bf16(float* c, const u32* a, const u32* b) {
    asm volatile(
        "mma.sync.aligned.m16n8k16.row.col.f32.bf16.bf16.f32 "
        "{%0,%1,%2,%3}, {%4,%5,%6,%7}, {%8,%9}, {%0,%1,%2,%3};"
        : "+f"(c[0]), "+f"(c[1]), "+f"(c[2]), "+f"(c[3])
        : "r"(a[0]), "r"(a[1]), "r"(a[2]), "r"(a[3]), "r"(b[0]), "r"(b[1]));
}
__device__ __forceinline__ void cpa16(u32 dst, const void* src, u32 sz) {
    asm volatile("cp.async.cg.shared.global [%0], [%1], 16, %2;"
                 :: "r"(dst), "l"(src), "r"(sz) : "memory");
}
#define CP_COMMIT() asm volatile("cp.async.commit_group;" ::: "memory")

__device__ __forceinline__ u32 swz(int r, int c) {
    return (u32)r * 64u + (u32)((c ^ ((r >> 1) & 3)) << 4);
}

#define MMAS(A, B) do {                                                        \
    _Pragma("unroll") for (int mi_ = 0; mi_ < 2; mi_++)                        \
        _Pragma("unroll") for (int ni_ = 0; ni_ < 4; ni_++) {                  \
            mma_bf16(acc[mi_][2 * ni_],     (A)[mi_], &(B)[ni_][0]);           \
            mma_bf16(acc[mi_][2 * ni_ + 1], (A)[mi_], &(B)[ni_][2]);           \
        }                                                                      \
} while (0)

#define MMAS1(P, A, B) do {                                                    \
    _Pragma("unroll") for (int ni_ = 0; ni_ < 4; ni_++) {                      \
        mma_bf16((P)[2 * ni_],     (A), &(B)[ni_][0]);                         \
        mma_bf16((P)[2 * ni_ + 1], (A), &(B)[ni_][2]);                         \
    }                                                                          \
} while (0)

#define MTB   8192
#define OFF_AH 0
#define OFF_AL (1 * MTB)
#define OFF_BH (2 * MTB)
#define OFF_BL (3 * MTB)
#define QSET  (4 * MTB)
#define SM_IDX (3 * QSET)
#define DSM   (SM_IDX + 1024)
#define LDC   132

__device__ __forceinline__ void store_split(
    __nv_bfloat16* fo, int row, int lane, float v0, float v1, float v2, float v3)
{
    __nv_bfloat16 h0 = __float2bfloat16(v0), h1 = __float2bfloat16(v1);
    __nv_bfloat16 h2 = __float2bfloat16(v2), h3 = __float2bfloat16(v3);
    __nv_bfloat162 hh0; hh0.x = h0; hh0.y = h1;
    __nv_bfloat162 hh1; hh1.x = h2; hh1.y = h3;
    uint2 H; H.x = *(u32*)&hh0; H.y = *(u32*)&hh1;
    uint2 L;
    L.x = pack_bf2(v0 - __bfloat162float(h0), v1 - __bfloat162float(h1));
    L.y = pack_bf2(v2 - __bfloat162float(h2), v3 - __bfloat162float(h3));
    char* base = (char*)fo + (size_t)row * 512 + lane * 8;
    *(uint2*)base = H;
    *(uint2*)(base + 256) = L;
}

__device__ __forceinline__ void load_hl(
    const __nv_bfloat16* fi, int row, int lane,
    float& r0, float& r1, float& r2, float& r3)
{
    const char* base = (const char*)fi + (size_t)row * 512 + lane * 8;
    uint2 H = *(const uint2*)base;
    uint2 L = *(const uint2*)(base + 256);
    __nv_bfloat162 h0 = *(__nv_bfloat162*)&H.x;
    __nv_bfloat162 h1 = *(__nv_bfloat162*)&H.y;
    __nv_bfloat162 l0 = *(__nv_bfloat162*)&L.x;
    __nv_bfloat162 l1 = *(__nv_bfloat162*)&L.y;
    r0 = __bfloat162float(h0.x) + __bfloat162float(l0.x);
    r1 = __bfloat162float(h0.y) + __bfloat162float(l0.y);
    r2 = __bfloat162float(h1.x) + __bfloat162float(l1.x);
    r3 = __bfloat162float(h1.y) + __bfloat162float(l1.y);
}

__device__ __forceinline__ float4 gn_row(float4 v, float4 g, float4 b) {
    float s1 = v.x + v.y + v.z + v.w;
    float s2 = v.x * v.x + v.y * v.y + v.z * v.z + v.w * v.w;
    #pragma unroll
    for (int o = 16; o >= 1; o >>= 1) {
        s1 += __shfl_xor_sync(0xffffffffu, s1, o);
        s2 += __shfl_xor_sync(0xffffffffu, s2, o);
    }
    float mu = s1 * (1.f / 128.f);
    float var = s2 * (1.f / 128.f) - mu * mu;
    float rs = rsqrtf(var + 1e-5f);
    return make_float4((v.x - mu) * rs * g.x + b.x, (v.y - mu) * rs * g.y + b.y,
                       (v.z - mu) * rs * g.z + b.z, (v.w - mu) * rs * g.w + b.w);
}

// ================= dense bf16x3 GEMM =================
__device__ __forceinline__ void stage_q_d(
    u32 smb, int q, int bi, int tid, int row0, int nrows,
    const __nv_bfloat16* Ahl,
    const __nv_bfloat16* WH, const __nv_bfloat16* WL)
{
    u32 bbase = smb + (u32)bi * QSET;
    #pragma unroll
    for (int j = 0; j < 2; j++) {
        int id = tid + j * 256;
        int r = id >> 2, sg = id & 3;
        u32 doff = swz(r, sg);
        u32 asz = 16;
        int gr = row0 + r;
        if (gr >= nrows) { asz = 0; gr = 0; }
        size_t abyte = (size_t)gr * 512 + (size_t)q * 64 + (size_t)sg * 16;
        cpa16(bbase + OFF_AH + doff, (const char*)Ahl + abyte, asz);
        cpa16(bbase + OFF_AL + doff, (const char*)Ahl + abyte + 256, asz);
        size_t wbyte = (size_t)r * 256 + (size_t)q * 64 + (size_t)sg * 16;
        cpa16(bbase + OFF_BH + doff, (const char*)WH + wbyte, 16);
        cpa16(bbase + OFF_BL + doff, (const char*)WL + wbyte, 16);
    }
    CP_COMMIT();
}

// EPI: 0 fp32 store (shuffle epilogue) | 3 extras + GN + relu + split (meta)
template<int EPI>
__global__ __launch_bounds__(256, 2) void hmma_gemm(
    const __nv_bfloat16* __restrict__ Ahl,
    const __nv_bfloat16* __restrict__ Whi, const __nv_bfloat16* __restrict__ Wlo,
    float* __restrict__ out,
    const float* __restrict__ gng, const float* __restrict__ gnb,
    __nv_bfloat16* __restrict__ fo,
    int nrows,
    const float* __restrict__ turn, const float* __restrict__ control,
    const float* __restrict__ inter, const float* __restrict__ wext)
{
    extern __shared__ char dsm[];
    const int tid = threadIdx.x;
    const int wid = tid >> 5;
    const int lane = tid & 31;
    const int row0 = blockIdx.x * 128;
    const u32 smb = cvta_sm(dsm);

    const int wm = (wid & 3) * 32;
    const int wn = (wid >> 2) * 64;

    float acc[2][8][4];
    #pragma unroll
    for (int mi = 0; mi < 2; mi++)
        #pragma unroll
        for (int nj = 0; nj < 8; nj++)
            #pragma unroll
            for (int q = 0; q < 4; q++) acc[mi][nj][q] = 0.f;

    const int ra = wm + (lane & 15);
    const u32 xa = (u32)((ra >> 1) & 3);
    const int ca = lane >> 4;
    const int rb = wn + (lane & 7) + ((lane >> 4) & 1) * 8;
    const u32 xb = (u32)((rb >> 1) & 3);
    const int cb = (lane >> 3) & 1;

    stage_q_d(smb, 0, 0, tid, row0, nrows, Ahl, Whi, Wlo);
    stage_q_d(smb, 1, 1, tid, row0, nrows, Ahl, Whi, Wlo);
    stage_q_d(smb, 2, 2, tid, row0, nrows, Ahl, Whi, Wlo);

    #pragma unroll
    for (int q = 0; q < 4; q++) {
        if (q <= 1)      asm volatile("cp.async.wait_group 2;" ::: "memory");
        else if (q == 2) asm volatile("cp.async.wait_group 1;" ::: "memory");
        else             asm volatile("cp.async.wait_group 0;" ::: "memory");
        __syncthreads();

        const u32 qb = smb + (u32)(q % 3) * QSET;
        #pragma unroll
        for (int ks = 0; ks < 2; ks++) {
            const u32 ach = (u32)(ks * 2 + ca) ^ xa;
            const u32 bch = (u32)(ks * 2 + cb) ^ xb;
            const u32 aoff = (u32)ra * 64u + (ach << 4);
            u32 a0[2][4], a1[2][4], b0[4][4], b1[4][4];
            ldm4(a0[0], qb + OFF_AH + aoff);
            ldm4(a0[1], qb + OFF_AH + aoff + 16 * 64);
            #pragma unroll
            for (int ni = 0; ni < 4; ni++)
                ldm4(b0[ni], qb + OFF_BH + (u32)(rb + ni * 16) * 64u + (bch << 4));
            MMAS(a0, b0);
            ldm4(a1[0], qb + OFF_AL + aoff);
            ldm4(a1[1], qb + OFF_AL + aoff + 16 * 64);
            MMAS(a1, b0);
            #pragma unroll
            for (int ni = 0; ni < 4; ni++)
                ldm4(b1[ni], qb + OFF_BL + (u32)(rb + ni * 16) * 64u + (bch << 4));
            MMAS(a0, b1);
        }

        if (q == 0) {
            __syncthreads();
            stage_q_d(smb, 3, 0, tid, row0, nrows, Ahl, Whi, Wlo);
        }
    }

    if (EPI == 0) {
        // direct fragment -> STG via pair shuffle (no smem C-tile, no syncs)
        #pragma unroll
        for (int mi = 0; mi < 2; mi++) {
            int r_e = row0 + wm + mi * 16 + (lane >> 2);
            int r_o = r_e + 8;
            int cbx = wn + ((lane >> 1) & 1) * 4;
            #pragma unroll
            for (int nj = 0; nj < 8; nj++) {
                float x0 = acc[mi][nj][0], x1 = acc[mi][nj][1];
                float y0 = acc[mi][nj][2], y1 = acc[mi][nj][3];
                float px0 = __shfl_xor_sync(0xffffffffu, x0, 1);
                float px1 = __shfl_xor_sync(0xffffffffu, x1, 1);
                float py0 = __shfl_xor_sync(0xffffffffu, y0, 1);
                float py1 = __shfl_xor_sync(0xffffffffu, y1, 1);
                int cc = cbx + nj * 8;
                if ((lane & 1) == 0) {
                    if (r_e < nrows)
                        *(float4*)(out + (size_t)r_e * C + cc) =
                            make_float4(x0, x1, px0, px1);
                } else {
                    if (r_o < nrows)
                        *(float4*)(out + (size_t)r_o * C + cc) =
                            make_float4(py0, py1, y0, y1);
                }
            }
        }
        return;
    }

    // ---- EPI 3: smem C-tile + row-wise epilogue ----
    __syncthreads();
    float* Csm = (float*)dsm;
    #pragma unroll
    for (int mi = 0; mi < 2; mi++)
        #pragma unroll
        for (int nj = 0; nj < 8; nj++) {
            int r = wm + mi * 16 + (lane >> 2);
            int c = wn + nj * 8 + (lane & 3) * 2;
            float* p = Csm + (size_t)r * LDC + c;
            p[0] = acc[mi][nj][0];
            p[1] = acc[mi][nj][1];
            p[8 * LDC] = acc[mi][nj][2];
            p[8 * LDC + 1] = acc[mi][nj][3];
        }
    __syncthreads();

    float4 gv = *(const float4*)(gng + lane * 4);
    float4 bv = *(const float4*)(gnb + lane * 4);
    float4 we[4];
    #pragma unroll
    for (int j = 0; j < 4; j++)
        we[j] = *(const float4*)(wext + (size_t)j * C + lane * 4);

    for (int i = 0; i < 16; i++) {
        int r = wid * 16 + i;
        int row = row0 + r;
        if (row >= nrows) continue;
        float4 v = *(float4*)(Csm + (size_t)r * LDC + lane * 4);
        float t0 = turn[2 * row], t1 = turn[2 * row + 1];
        float cc0 = control[row], it = inter[row];
        v.x += t0 * we[0].x + t1 * we[1].x + cc0 * we[2].x + it * we[3].x;
        v.y += t0 * we[0].y + t1 * we[1].y + cc0 * we[2].y + it * we[3].y;
        v.z += t0 * we[0].z + t1 * we[1].z + cc0 * we[2].z + it * we[3].z;
        v.w += t0 * we[0].w + t1 * we[1].w + cc0 * we[2].w + it * we[3].w;
        float4 o = gn_row(v, gv, bv);
        store_split(fo, row, lane, fmaxf(o.x, 0.f), fmaxf(o.y, 0.f),
                    fmaxf(o.z, 0.f), fmaxf(o.w, 0.f));
    }
}

// ============ edge GEMM: all pre/suc/left/right in one launch, RED into T ========
// (smem C-tile epilogue — measured faster than register shuffle for the RED path)
__global__ __launch_bounds__(256, 2) void edge_gemm(
    const __nv_bfloat16* __restrict__ Ahl,
    const __nv_bfloat16* __restrict__ Whi, const __nv_bfloat16* __restrict__ Wlo,
    float* __restrict__ T,
    const int* __restrict__ pre, const int* __restrict__ suc,
    const int* __restrict__ left, const int* __restrict__ right,
    int layer)
{
    const int y = blockIdx.y;
    const int* dbase;
    int nedges;
    size_t wslot;
    if (y < 6) {
        dbase = pre + (size_t)y * 2 * EP; nedges = EP;
        wslot = OFF_PS + (size_t)(layer * 12 + y) * CC;
    } else if (y < 12) {
        dbase = suc + (size_t)(y - 6) * 2 * EP; nedges = EP;
        wslot = OFF_PS + (size_t)(layer * 12 + y) * CC;
    } else {
        if (blockIdx.x >= 196) return;
        dbase = (y == 12) ? left : right; nedges = EL;
        wslot = OFF_LR + (size_t)(layer * 2 + (y - 12)) * CC;
    }
    const int* sbase = dbase + nedges;

    extern __shared__ char dsm[];
    const int tid = threadIdx.x;
    const int wid = tid >> 5;
    const int lane = tid & 31;
    const u32 smb = cvta_sm(dsm);
    int* s_dst = (int*)(dsm + SM_IDX);
    int* s_src = s_dst + 128;

    const __nv_bfloat16* WH = Whi + wslot;
    const __nv_bfloat16* WL = Wlo + wslot;

    if (tid < 128) {
        int e = blockIdx.x * 128 + tid;
        s_dst[tid] = (e < nedges) ? dbase[e] : -1;
        s_src[tid] = (e < nedges) ? sbase[e] : 0;
    }
    __syncthreads();

    const int wm = (wid & 3) * 32;
    const int wn = (wid >> 2) * 64;

    float acc[2][8][4];
    #pragma unroll
    for (int mi = 0; mi < 2; mi++)
        #pragma unroll
        for (int nj = 0; nj < 8; nj++)
            #pragma unroll
            for (int q = 0; q < 4; q++) acc[mi][nj][q] = 0.f;

    const int ra = wm + (lane & 15);
    const u32 xa = (u32)((ra >> 1) & 3);
    const int ca = lane >> 4;
    const int rb = wn + (lane & 7) + ((lane >> 4) & 1) * 8;
    const u32 xb = (u32)((rb >> 1) & 3);
    const int cb = (lane >> 3) & 1;

    #define STAGE_QG(qq, bi) do {                                              \
        u32 bbase_ = smb + (u32)(bi) * QSET;                                   \
        _Pragma("unroll") for (int j = 0; j < 2; j++) {                        \
            int id = tid + j * 256;                                            \
            int r = id >> 2, sg = id & 3;                                      \
            u32 doff = swz(r, sg);                                             \
            size_t abyte = (size_t)s_src[r] * 512 + (size_t)(qq) * 64 + (size_t)sg * 16; \
            cpa16(bbase_ + OFF_AH + doff, (const char*)Ahl + abyte, 16);       \
            cpa16(bbase_ + OFF_AL + doff, (const char*)Ahl + abyte + 256, 16); \
            size_t wbyte = (size_t)r * 256 + (size_t)(qq) * 64 + (size_t)sg * 16; \
            cpa16(bbase_ + OFF_BH + doff, (const char*)WH + wbyte, 16);        \
            cpa16(bbase_ + OFF_BL + doff, (const char*)WL + wbyte, 16);        \
        }                                                                      \
        CP_COMMIT();                                                           \
    } while (0)

    STAGE_QG(0, 0);
    STAGE_QG(1, 1);
    STAGE_QG(2, 2);

    #pragma unroll
    for (int q = 0; q < 4; q++) {
        if (q <= 1)      asm volatile("cp.async.wait_group 2;" ::: "memory");
        else if (q == 2) asm volatile("cp.async.wait_group 1;" ::: "memory");
        else             asm volatile("cp.async.wait_group 0;" ::: "memory");
        __syncthreads();

        const u32 qb = smb + (u32)(q % 3) * QSET;
        #pragma unroll
        for (int ks = 0; ks < 2; ks++) {
            const u32 ach = (u32)(ks * 2 + ca) ^ xa;
            const u32 bch = (u32)(ks * 2 + cb) ^ xb;
            const u32 aoff = (u32)ra * 64u + (ach << 4);
            u32 a0[2][4], a1[2][4], b0[4][4], b1[4][4];
            ldm4(a0[0], qb + OFF_AH + aoff);
            ldm4(a0[1], qb + OFF_AH + aoff + 16 * 64);
            #pragma unroll
            for (int ni = 0; ni < 4; ni++)
                ldm4(b0[ni], qb + OFF_BH + (u32)(rb + ni * 16) * 64u + (bch << 4));
            MMAS(a0, b0);
            ldm4(a1[0], qb + OFF_AL + aoff);
            ldm4(a1[1], qb + OFF_AL + aoff + 16 * 64);
            MMAS(a1, b0);
            #pragma unroll
            for (int ni = 0; ni < 4; ni++)
                ldm4(b1[ni], qb + OFF_BL + (u32)(rb + ni * 16) * 64u + (bch << 4));
            MMAS(a0, b1);
        }

        if (q == 0) {
            __syncthreads();
            STAGE_QG(3, 0);
        }
    }
    #undef STAGE_QG

    __syncthreads();
    float* Csm = (float*)dsm;
    #pragma unroll
    for (int mi = 0; mi < 2; mi++)
        #pragma unroll
        for (int nj = 0; nj < 8; nj++) {
            int r = wm + mi * 16 + (lane >> 2);
            int c = wn + nj * 8 + (lane & 3) * 2;
            float* p = Csm + (size_t)r * LDC + c;
            p[0] = acc[mi][nj][0];
            p[1] = acc[mi][nj][1];
            p[8 * LDC] = acc[mi][nj][2];
            p[8 * LDC + 1] = acc[mi][nj][3];
        }
    __syncthreads();

    for (int i = 0; i < 16; i++) {
        int r = wid * 16 + i;
        int dd = s_dst[r];
        if (dd < 0) continue;
        float4 v = *(float4*)(Csm + (size_t)r * LDC + lane * 4);
        red4(T + (size_t)dd * C + lane * 4, v.x, v.y, v.z, v.w);
    }
}

// ======== gn_gemm: A = relu(gn(T)) in-kernel, C = A @ W, residual from bf16 hi/lo ==
#define G_AH   0
#define G_AL   32768
#define G_B    65536
#define G_DSM  98304

__global__ __launch_bounds__(256, 2) void gn_gemm(
    const float* __restrict__ Tg,
    const float* __restrict__ ing, const float* __restrict__ inb,
    const __nv_bfloat16* __restrict__ Whi, const __nv_bfloat16* __restrict__ Wlo,
    float* __restrict__ wout,
    const float* __restrict__ outg, const float* __restrict__ outb,
    const __nv_bfloat16* __restrict__ addhl,
    __nv_bfloat16* __restrict__ fo,
    int nrows)
{
    extern __shared__ char dsm[];
    const int tid = threadIdx.x;
    const int wid = tid >> 5;
    const int lane = tid & 31;
    const int row0 = blockIdx.x * 128;
    const u32 smb = cvta_sm(dsm);

    #define STAGE_B2(qq, bi) do {                                              \
        u32 bb_ = smb + G_B + (u32)(bi) * 16384u;                              \
        _Pragma("unroll") for (int j = 0; j < 2; j++) {                        \
            int id = tid + j * 256;                                            \
            int r = id >> 2, sg = id & 3;                                      \
            u32 doff = swz(r, sg);                                             \
            size_t wbyte = (size_t)r * 256 + (size_t)(qq) * 64 + (size_t)sg * 16; \
            cpa16(bb_ + doff, (const char*)Whi + wbyte, 16);                   \
            cpa16(bb_ + 8192u + doff, (const char*)Wlo + wbyte, 16);           \
        }                                                                      \
        CP_COMMIT();                                                           \
    } while (0)

    STAGE_B2(0, 0);
    STAGE_B2(1, 1);

    {
        float4 gin = *(const float4*)(ing + lane * 4);
        float4 bin = *(const float4*)(inb + lane * 4);
        const int q  = lane >> 3;
        const int c  = (lane >> 1) & 3;
        const int o8 = (lane & 1) * 8;
        #pragma unroll 4
        for (int it = 0; it < 16; it++) {
            int r = wid + it * 8;
            int row = row0 + r;
            float4 v = make_float4(0.f, 0.f, 0.f, 0.f);
            if (row < nrows) v = *(const float4*)(Tg + (size_t)row * C + lane * 4);
            float4 o = gn_row(v, gin, bin);
            float v0 = fmaxf(o.x, 0.f), v1 = fmaxf(o.y, 0.f);
            float v2 = fmaxf(o.z, 0.f), v3 = fmaxf(o.w, 0.f);
            __nv_bfloat16 h0 = __float2bfloat16(v0), h1 = __float2bfloat16(v1);
            __nv_bfloat16 h2 = __float2bfloat16(v2), h3 = __float2bfloat16(v3);
            __nv_bfloat162 hh0; hh0.x = h0; hh0.y = h1;
            __nv_bfloat162 hh1; hh1.x = h2; hh1.y = h3;
            uint2 H; H.x = *(u32*)&hh0; H.y = *(u32*)&hh1;
            uint2 L;
            L.x = pack_bf2(v0 - __bfloat162float(h0), v1 - __bfloat162float(h1));
            L.y = pack_bf2(v2 - __bfloat162float(h2), v3 - __bfloat162float(h3));
            u32 off = (u32)q * 8192u + swz(r, c) + (u32)o8;
            *(uint2*)(dsm + G_AH + off) = H;
            *(uint2*)(dsm + G_AL + off) = L;
        }
    }

    const int wm = (wid & 3) * 32;
    const int wn = (wid >> 2) * 64;

    float acc[2][8][4];
    #pragma unroll
    for (int mi = 0; mi < 2; mi++)
        #pragma unroll
        for (int nj = 0; nj < 8; nj++)
            #pragma unroll
            for (int q = 0; q < 4; q++) acc[mi][nj][q] = 0.f;

    const int ra = wm + (lane & 15);
    const u32 xa = (u32)((ra >> 1) & 3);
    const int ca = lane >> 4;
    const int rb = wn + (lane & 7) + ((lane >> 4) & 1) * 8;
    const u32 xb = (u32)((rb >> 1) & 3);
    const int cb = (lane >> 3) & 1;

    #pragma unroll
    for (int q = 0; q < 4; q++) {
        if (q < 3) asm volatile("cp.async.wait_group 1;" ::: "memory");
        else       asm volatile("cp.async.wait_group 0;" ::: "memory");
        __syncthreads();

        const u32 aqh = smb + G_AH + (u32)q * 8192u;
        const u32 aql = smb + G_AL + (u32)q * 8192u;
        const u32 bqh = smb + G_B + (u32)(q & 1) * 16384u;
        const u32 bql = bqh + 8192u;
        #pragma unroll
        for (int ks = 0; ks < 2; ks++) {
            const u32 ach = (u32)(ks * 2 + ca) ^ xa;
            const u32 bch = (u32)(ks * 2 + cb) ^ xb;
            const u32 aoff = (u32)ra * 64u + (ach << 4);
            u32 a0[2][4], a1[2][4], b0[4][4], b1[4][4];
            ldm4(a0[0], aqh + aoff);
            ldm4(a0[1], aqh + aoff + 16 * 64);
            #pragma unroll
            for (int ni = 0; ni < 4; ni++)
                ldm4(b0[ni], bqh + (u32)(rb + ni * 16) * 64u + (bch << 4));
            MMAS(a0, b0);
            ldm4(a1[0], aql + aoff);
            ldm4(a1[1], aql + aoff + 16 * 64);
            MMAS(a1, b0);
            #pragma unroll
            for (int ni = 0; ni < 4; ni++)
                ldm4(b1[ni], bql + (u32)(rb + ni * 16) * 64u + (bch << 4));
            MMAS(a0, b1);
        }

        if (q < 2) {
            __syncthreads();
            STAGE_B2(q + 2, q & 1);
        }
    }
    #undef STAGE_B2

    __syncthreads();
    float* Csm = (float*)dsm;
    #pragma unroll
    for (int mi = 0; mi < 2; mi++)
        #pragma unroll
        for (int nj = 0; nj < 8; nj++) {
            int r = wm + mi * 16 + (lane >> 2);
            int c = wn + nj * 8 + (lane & 3) * 2;
            float* p = Csm + (size_t)r * LDC + c;
            p[0] = acc[mi][nj][0];
            p[1] = acc[mi][nj][1];
            p[8 * LDC] = acc[mi][nj][2];
            p[8 * LDC + 1] = acc[mi][nj][3];
        }
    __syncthreads();

    float4 gv = *(const float4*)(outg + lane * 4);
    float4 bv = *(const float4*)(outb + lane * 4);

    for (int i = 0; i < 16; i++) {
        int r = wid * 16 + i;
        int row = row0 + r;
        if (row >= nrows) continue;
        float4 v = *(float4*)(Csm + (size_t)r * LDC + lane * 4);
        float4 o = gn_row(v, gv, bv);
        float r0, r1, r2, r3;
        load_hl(addhl, row, lane, r0, r1, r2, r3);
        float v0 = fmaxf(o.x + r0, 0.f);
        float v1 = fmaxf(o.y + r1, 0.f);
        float v2 = fmaxf(o.z + r2, 0.f);
        float v3 = fmaxf(o.w + r3, 0.f);
        if (wout)
            *(float4*)(wout + (size_t)row * C + lane * 4) = make_float4(v0, v1, v2, v3);
        store_split(fo, row, lane, v0, v1, v2, v3);
    }
}

// ======== dual_gemm: fused prologue in2+seg2 =========================
#define D_QA  0
#define D_QB  16384
#define D_QSET 49152
#define D_DSM  98304
#define LDC64  132

__global__ __launch_bounds__(256, 2) void dual_gemm(
    const __nv_bfloat16* __restrict__ H1, const __nv_bfloat16* __restrict__ H2,
    const __nv_bfloat16* __restrict__ Whi, const __nv_bfloat16* __restrict__ Wlo,
    const float* __restrict__ g1, const float* __restrict__ b1,
    const float* __restrict__ g2, const float* __restrict__ b2,
    __nv_bfloat16* __restrict__ fo, int nrows)
{
    extern __shared__ char dsm[];
    const int tid = threadIdx.x;
    const int wid = tid >> 5;
    const int lane = tid & 31;
    const int row0 = blockIdx.x * 64;
    const u32 smb = cvta_sm(dsm);

    const __nv_bfloat16* W1h = Whi + OFF_IN2;
    const __nv_bfloat16* W1l = Wlo + OFF_IN2;
    const __nv_bfloat16* W2h = Whi + OFF_SEG2;
    const __nv_bfloat16* W2l = Wlo + OFF_SEG2;

    #define STAGE_D(qq, bi) do {                                               \
        u32 qa_ = smb + (u32)(bi) * D_QSET + D_QA;                             \
        u32 qb_ = smb + (u32)(bi) * D_QSET + D_QB;                             \
        {                                                                      \
            int r = tid >> 2, sg = tid & 3;                                    \
            u32 doff = swz(r, sg);                                             \
            u32 asz = 16;                                                      \
            int gr = row0 + r;                                                 \
            if (gr >= nrows) { asz = 0; gr = 0; }                              \
            size_t ab = (size_t)gr * 512 + (size_t)(qq) * 64 + (size_t)sg * 16; \
            cpa16(qa_ + 0u     + doff, (const char*)H1 + ab, asz);             \
            cpa16(qa_ + 4096u  + doff, (const char*)H1 + ab + 256, asz);       \
            cpa16(qa_ + 8192u  + doff, (const char*)H2 + ab, asz);             \
            cpa16(qa_ + 12288u + doff, (const char*)H2 + ab + 256, asz);       \
        }                                                                      \
        _Pragma("unroll") for (int j = 0; j < 2; j++) {                        \
            int id = tid + j * 256;                                            \
            int r = id >> 2, sg = id & 3;                                      \
            u32 doff = swz(r, sg);                                             \
            size_t wb = (size_t)r * 256 + (size_t)(qq) * 64 + (size_t)sg * 16; \
            cpa16(qb_ + 0u      + doff, (const char*)W1h + wb, 16);            \
            cpa16(qb_ + 8192u   + doff, (const char*)W1l + wb, 16);            \
            cpa16(qb_ + 16384u  + doff, (const char*)W2h + wb, 16);            \
            cpa16(qb_ + 24576u  + doff, (const char*)W2l + wb, 16);            \
        }                                                                      \
        CP_COMMIT();                                                           \
    } while (0)

    STAGE_D(0, 0);
    STAGE_D(1, 1);

    const int wm = (wid & 3) * 16;
    const int wn = (wid >> 2) * 64;

    float accP[8][4], accQ[8][4];
    #pragma unroll
    for (int nj = 0; nj < 8; nj++)
        #pragma unroll
        for (int q = 0; q < 4; q++) { accP[nj][q] = 0.f; accQ[nj][q] = 0.f; }

    const int ra = wm + (lane & 15);
    const u32 xa = (u32)((ra >> 1) & 3);
    const int ca = lane >> 4;
    const int rb = wn + (lane & 7) + ((lane >> 4) & 1) * 8;
    const u32 xb = (u32)((rb >> 1) & 3);
    const int cb = (lane >> 3) & 1;

    #pragma unroll
    for (int q = 0; q < 4; q++) {
        if (q < 3) asm volatile("cp.async.wait_group 1;" ::: "memory");
        else       asm volatile("cp.async.wait_group 0;" ::: "memory");
        __syncthreads();

        const u32 qa = smb + (u32)(q & 1) * D_QSET + D_QA;
        const u32 qb = smb + (u32)(q & 1) * D_QSET + D_QB;
        #pragma unroll
        for (int ks = 0; ks < 2; ks++) {
            const u32 ach = (u32)(ks * 2 + ca) ^ xa;
            const u32 bch = (u32)(ks * 2 + cb) ^ xb;
            const u32 aoff = (u32)ra * 64u + (ach << 4);
            u32 a0[4], a1[4], b0[4][4], b1[4][4];
            ldm4(a0, qa + aoff);
            #pragma unroll
            for (int ni = 0; ni < 4; ni++)
                ldm4(b0[ni], qb + (u32)(rb + ni * 16) * 64u + (bch << 4));
            MMAS1(accP, a0, b0);
            ldm4(a1, qa + 4096u + aoff);
            MMAS1(accP, a1, b0);
            #pragma unroll
            for (int ni = 0; ni < 4; ni++)
                ldm4(b1[ni], qb + 8192u + (u32)(rb + ni * 16) * 64u + (bch << 4));
            MMAS1(accP, a0, b1);
            ldm4(a0, qa + 8192u + aoff);
            #pragma unroll
            for (int ni = 0; ni < 4; ni++)
                ldm4(b0[ni], qb + 16384u + (u32)(rb + ni * 16) * 64u + (bch << 4));
            MMAS1(accQ, a0, b0);
            ldm4(a1, qa + 12288u + aoff);
            MMAS1(accQ, a1, b0);
            #pragma unroll
            for (int ni = 0; ni < 4; ni++)
                ldm4(b1[ni], qb + 24576u + (u32)(rb + ni * 16) * 64u + (bch << 4));
            MMAS1(accQ, a0, b1);
        }

        if (q < 2) {
            __syncthreads();
            STAGE_D(q + 2, q & 1);
        }
    }
    #undef STAGE_D

    __syncthreads();
    float* CsmP = (float*)dsm;
    float* CsmQ = (float*)(dsm + 64 * LDC64 * 4);
    #pragma unroll
    for (int nj = 0; nj < 8; nj++) {
        int r = wm + (lane >> 2);
        int c = wn + nj * 8 + (lane & 3) * 2;
        float* p = CsmP + (size_t)r * LDC64 + c;
        p[0] = accP[nj][0]; p[1] = accP[nj][1];
        p[8 * LDC64] = accP[nj][2]; p[8 * LDC64 + 1] = accP[nj][3];
        float* qp = CsmQ + (size_t)r * LDC64 + c;
        qp[0] = accQ[nj][0]; qp[1] = accQ[nj][1];
        qp[8 * LDC64] = accQ[nj][2]; qp[8 * LDC64 + 1] = accQ[nj][3];
    }
    __syncthreads();

    float4 g1v = *(const float4*)(g1 + lane * 4);
    float4 b1v = *(const float4*)(b1 + lane * 4);
    float4 g2v = *(const float4*)(g2 + lane * 4);
    float4 b2v = *(const float4*)(b2 + lane * 4);

    for (int i = 0; i < 8; i++) {
        int r = wid * 8 + i;
        int row = row0 + r;
        if (row >= nrows) continue;
        float4 vp = *(float4*)(CsmP + (size_t)r * LDC64 + lane * 4);
        float4 vq = *(float4*)(CsmQ + (size_t)r * LDC64 + lane * 4);
        float4 a = gn_row(vp, g1v, b1v);
        float4 b = gn_row(vq, g2v, b2v);
        store_split(fo, row, lane,
                    fmaxf(a.x + b.x, 0.f), fmaxf(a.y + b.y, 0.f),
                    fmaxf(a.z + b.z, 0.f), fmaxf(a.w + b.w, 0.f));
    }
}

// ================= fused prep kernel =================
#define PREP_COPY_B 1563
#define PREP_W_B    4288
#define PREP_IN_B   25000

__global__ void prep(
    const float* __restrict__ ctrs, const float* __restrict__ feats,
    const float* __restrict__ w_in1, const float* __restrict__ b_in1,
    const float* __restrict__ w_seg1, const float* __restrict__ b_seg1,
    const float* __restrict__ w_in2, const float* __restrict__ w_seg2,
    const float* __restrict__ w_meta,
    const float* __restrict__ ctr_w, const float* __restrict__ pre_w,
    const float* __restrict__ suc_w, const float* __restrict__ left_w,
    const float* __restrict__ right_w, const float* __restrict__ ctr2_w,
    __nv_bfloat16* __restrict__ whi, __nv_bfloat16* __restrict__ wlo,
    __nv_bfloat16* __restrict__ h1, __nv_bfloat16* __restrict__ h2,
    float* __restrict__ out_tail)
{
    int b = blockIdx.x;
    int tid = threadIdx.x;
    if (b < PREP_COPY_B) {
        int i = b * 256 + tid;
        if (i < N_NODES * 2) out_tail[i] = ctrs[i];
        return;
    }
    b -= PREP_COPY_B;
    if (b < PREP_W_B) {
        int idx = b * 256 + tid;
        int mat = idx >> 14;
        int rem = idx & 16383;
        int k = rem >> 7, n = rem & 127;
        const float* src;
        if      (mat == 0) src = w_in2 + rem;
        else if (mat == 1) src = w_seg2 + rem;
        else if (mat == 2) src = w_meta + rem;
        else if (mat < 51) {
            int m = mat - 3; int i = m / 12; int r = m % 12;
            src = (r < 6) ? pre_w + (size_t)(i * 6 + r) * CC + rem
                          : suc_w + (size_t)(i * 6 + r - 6) * CC + rem;
        } else if (mat < 59) {
            int m = mat - 51; int i = m >> 1;
            src = ((m & 1) ? right_w : left_w) + (size_t)i * CC + rem;
        } else if (mat < 63) src = ctr_w  + (size_t)(mat - 59) * CC + rem;
        else                 src = ctr2_w + (size_t)(mat - 63) * CC + rem;
        float x = *src;
        __nv_bfloat16 h = __float2bfloat16(x);
        size_t o = (size_t)mat * CC + (size_t)n * C + k;
        whi[o] = h;
        wlo[o] = __float2bfloat16(x - __bfloat162float(h));
        return;
    }
    b -= PREP_W_B;
    {
        int i = b * 256 + tid;
        int n = i >> 5, lane = i & 31;
        float x0 = ctrs[2 * n], x1 = ctrs[2 * n + 1];
        float4 wa = *(const float4*)(w_in1 + lane * 4);
        float4 wb = *(const float4*)(w_in1 + C + lane * 4);
        float4 bb = *(const float4*)(b_in1 + lane * 4);
        float a0 = fmaxf(x0 * wa.x + x1 * wb.x + bb.x, 0.f);
        float a1 = fmaxf(x0 * wa.y + x1 * wb.y + bb.y, 0.f);
        float a2 = fmaxf(x0 * wa.z + x1 * wb.z + bb.z, 0.f);
        float a3 = fmaxf(x0 * wa.w + x1 * wb.w + bb.w, 0.f);
        store_split(h1, n, lane, a0, a1, a2, a3);
        float y0 = feats[2 * n], y1 = feats[2 * n + 1];
        float4 wc = *(const float4*)(w_seg1 + lane * 4);
        float4 wd = *(const float4*)(w_seg1 + C + lane * 4);
        float4 bd = *(const float4*)(b_seg1 + lane * 4);
        float c0 = fmaxf(y0 * wc.x + y1 * wd.x + bd.x, 0.f);
        float c1 = fmaxf(y0 * wc.y + y1 * wd.y + bd.y, 0.f);
        float c2 = fmaxf(y0 * wc.z + y1 * wd.z + bd.z, 0.f);
        float c3 = fmaxf(y0 * wc.w + y1 * wd.w + bd.w, 0.f);
        store_split(h2, n, lane, c0, c1, c2, c3);
    }
}

// ================= host launcher =================
extern "C" void kernel_launch(void* const* d_in, const int* in_sizes, int n_in,
                              void* d_out, int out_size)
{
    const float* control  = (const float*)d_in[0];
    const float* turn     = (const float*)d_in[1];
    const float* inter    = (const float*)d_in[2];
    const float* ctrs     = (const float*)d_in[3];
    const float* feats    = (const float*)d_in[4];
    const int*   pre      = (const int*)d_in[5];
    const int*   suc      = (const int*)d_in[6];
    const int*   left     = (const int*)d_in[7];
    const int*   right    = (const int*)d_in[8];
    const float* w_in1    = (const float*)d_in[9];
    const float* b_in1    = (const float*)d_in[10];
    const float* w_in2    = (const float*)d_in[11];
    const float* gn_in_g  = (const float*)d_in[12];
    const float* gn_in_b  = (const float*)d_in[13];
    const float* w_seg1   = (const float*)d_in[14];
    const float* b_seg1   = (const float*)d_in[15];
    const float* w_seg2   = (const float*)d_in[16];
    const float* gn_seg_g = (const float*)d_in[17];
    const float* gn_seg_b = (const float*)d_in[18];
    const float* w_meta   = (const float*)d_in[19];
    const float* gn_m_g   = (const float*)d_in[20];
    const float* gn_m_b   = (const float*)d_in[21];
    const float* ctr_w    = (const float*)d_in[22];
    const float* pre_w    = (const float*)d_in[23];
    const float* suc_w    = (const float*)d_in[24];
    const float* left_w   = (const float*)d_in[25];
    const float* right_w  = (const float*)d_in[26];
    const float* norm_g   = (const float*)d_in[27];
    const float* norm_b   = (const float*)d_in[28];
    const float* ctr2_w   = (const float*)d_in[29];
    const float* ctr2_g   = (const float*)d_in[30];
    const float* ctr2_b   = (const float*)d_in[31];

    float* T;
    __nv_bfloat16 *Fhl, *Xhl, *Whi, *Wlo;
    cudaGetSymbolAddress((void**)&T, g_T);
    cudaGetSymbolAddress((void**)&Fhl, g_Fhl);
    cudaGetSymbolAddress((void**)&Xhl, g_Xhl);
    cudaGetSymbolAddress((void**)&Whi, g_Whi);
    cudaGetSymbolAddress((void**)&Wlo, g_Wlo);

    cudaFuncSetAttribute(hmma_gemm<0>, cudaFuncAttributeMaxDynamicSharedMemorySize, DSM);
    cudaFuncSetAttribute(hmma_gemm<3>, cudaFuncAttributeMaxDynamicSharedMemorySize, DSM);
    cudaFuncSetAttribute(edge_gemm, cudaFuncAttributeMaxDynamicSharedMemorySize, DSM);
    cudaFuncSetAttribute(gn_gemm, cudaFuncAttributeMaxDynamicSharedMemorySize, G_DSM);
    cudaFuncSetAttribute(dual_gemm, cudaFuncAttributeMaxDynamicSharedMemorySize, D_DSM);

    const int NB = (N_NODES + 127) / 128;
    const int NB64 = (N_NODES + 63) / 64;
    const int NBP = (EP + 127) / 128;   // 782
    const float* wext = w_meta + 128 * C;

    prep<<<PREP_COPY_B + PREP_W_B + PREP_IN_B, 256>>>(
        ctrs, feats, w_in1, b_in1, w_seg1, b_seg1,
        w_in2, w_seg2, w_meta, ctr_w, pre_w, suc_w, left_w, right_w, ctr2_w,
        Whi, Wlo, Xhl, Fhl, (float*)d_out + (size_t)N_NODES * C);
    dual_gemm<<<NB64, 256, D_DSM>>>(Xhl, Fhl, Whi, Wlo,
        gn_in_g, gn_in_b, gn_seg_g, gn_seg_b, Xhl, N_NODES);
    hmma_gemm<3><<<NB, 256, DSM>>>(Xhl, Whi + OFF_META, Wlo + OFF_META,
        nullptr, gn_m_g, gn_m_b, Fhl, N_NODES,
        turn, control, inter, wext);

    for (int i = 0; i < 4; i++) {
        float* wout = (i == 3) ? (float*)d_out : nullptr;

        hmma_gemm<0><<<NB, 256, DSM>>>(
            Fhl, Whi + OFF_CTR + (size_t)i * CC, Wlo + OFF_CTR + (size_t)i * CC,
            T, nullptr, nullptr, nullptr, N_NODES,
            nullptr, nullptr, nullptr, nullptr);
        edge_gemm<<<dim3(NBP, 14), 256, DSM>>>(
            Fhl, Whi, Wlo, T, pre, suc, left, right, i);
        gn_gemm<<<NB, 256, G_DSM>>>(
            T, norm_g + (size_t)i * C, norm_b + (size_t)i * C,
            Whi + OFF_CTR2 + (size_t)i * CC, Wlo + OFF_CTR2 + (size_t)i * CC,
            wout, ctr2_g + (size_t)i * C, ctr2_b + (size_t)i * C, Fhl,
            Fhl, N_NODES);
    }
}

// round 15
// speedup vs baseline: 1.0486x; 1.0087x over previous
#include <cuda_runtime.h>
#include <cuda_bf16.h>
#include <cstdint>
#include <cstddef>

#define N_NODES 200000
#define C 128
#define S 6
#define EP 100000
#define EL 25000
#define CC 16384

typedef unsigned long long u64;
typedef unsigned int u32;

// ---- static device scratch ----
__device__ float g_T[(size_t)N_NODES * C];
__device__ __nv_bfloat16 g_Fhl[(size_t)N_NODES * 256];
__device__ __nv_bfloat16 g_Xhl[(size_t)N_NODES * 256];
__device__ __nv_bfloat16 g_Whi[(size_t)67 * CC];
__device__ __nv_bfloat16 g_Wlo[(size_t)67 * CC];

#define OFF_IN2   0
#define OFF_SEG2  (1 * CC)
#define OFF_META  (2 * CC)
#define OFF_PS    (3 * CC)
#define OFF_LR    (51 * CC)
#define OFF_CTR   (59 * CC)
#define OFF_CTR2  (63 * CC)

// ---- helpers ----
__device__ __forceinline__ u32 cvta_sm(const void* p) {
    u32 a;
    asm("{ .reg .u64 t; cvta.to.shared.u64 t, %1; cvt.u32.u64 %0, t; }" : "=r"(a) : "l"(p));
    return a;
}
__device__ __forceinline__ void red4(float* p, float a, float b, float c, float d) {
    asm volatile("red.global.add.v4.f32 [%0], {%1,%2,%3,%4};"
                 :: "l"(p), "f"(a), "f"(b), "f"(c), "f"(d) : "memory");
}
__device__ __forceinline__ u32 pack_bf2(float a, float b) {
    __nv_bfloat162 t = __floats2bfloat162_rn(a, b);
    return *(u32*)&t;
}
__device__ __forceinline__ void ldm4(u32* r, u32 addr) {
    asm volatile("ldmatrix.sync.aligned.m8n8.x4.shared.b16 {%0,%1,%2,%3}, [%4];"
                 : "=r"(r[0]), "=r"(r[1]), "=r"(r[2]), "=r"(r[3]) : "r"(addr));
}
__device__ __forceinline__ void mma_bf16(float* c, const u32* a, const u32* b) {
    asm volatile(
        "mma.sync.aligned.m16n8k16.row.col.f32.bf16.bf16.f32 "
        "{%0,%1,%2,%3}, {%4,%5,%6,%7}, {%8,%9}, {%0,%1,%2,%3};"
        : "+f"(c[0]), "+f"(c[1]), "+f"(c[2]), "+f"(c[3])
        : "r"(a[0]), "r"(a[1]), "r"(a[2]), "r"(a[3]), "r"(b[0]), "r"(b[1]));
}
__device__ __forceinline__ void cpa16(u32 dst, const void* src, u32 sz) {
    asm volatile("cp.async.cg.shared.global [%0], [%1], 16, %2;"
                 :: "r"(dst), "l"(src), "r"(sz) : "memory");
}
#define CP_COMMIT() asm volatile("cp.async.commit_group;" ::: "memory")

__device__ __forceinline__ u32 swz(int r, int c) {
    return (u32)r * 64u + (u32)((c ^ ((r >> 1) & 3)) << 4);
}

#define MMAS(A, B) do {                                                        \
    _Pragma("unroll") for (int mi_ = 0; mi_ < 2; mi_++)                        \
        _Pragma("unroll") for (int ni_ = 0; ni_ < 4; ni_++) {                  \
            mma_bf16(acc[mi_][2 * ni_],     (A)[mi_], &(B)[ni_][0]);           \
            mma_bf16(acc[mi_][2 * ni_ + 1], (A)[mi_], &(B)[ni_][2]);           \
        }                                                                      \
} while (0)

#define MMAS1(P, A, B) do {                                                    \
    _Pragma("unroll") for (int ni_ = 0; ni_ < 4; ni_++) {                      \
        mma_bf16((P)[2 * ni_],     (A), &(B)[ni_][0]);                         \
        mma_bf16((P)[2 * ni_ + 1], (A), &(B)[ni_][2]);                         \
    }                                                                          \
} while (0)

#define MTB   8192
#define OFF_AH 0
#define OFF_AL (1 * MTB)
#define OFF_BH (2 * MTB)
#define OFF_BL (3 * MTB)
#define QSET  (4 * MTB)
#define SM_IDX (3 * QSET)
#define DSM   (SM_IDX + 1024)
#define LDC   132

__device__ __forceinline__ void store_split(
    __nv_bfloat16* fo, int row, int lane, float v0, float v1, float v2, float v3)
{
    __nv_bfloat16 h0 = __float2bfloat16(v0), h1 = __float2bfloat16(v1);
    __nv_bfloat16 h2 = __float2bfloat16(v2), h3 = __float2bfloat16(v3);
    __nv_bfloat162 hh0; hh0.x = h0; hh0.y = h1;
    __nv_bfloat162 hh1; hh1.x = h2; hh1.y = h3;
    uint2 H; H.x = *(u32*)&hh0; H.y = *(u32*)&hh1;
    uint2 L;
    L.x = pack_bf2(v0 - __bfloat162float(h0), v1 - __bfloat162float(h1));
    L.y = pack_bf2(v2 - __bfloat162float(h2), v3 - __bfloat162float(h3));
    char* base = (char*)fo + (size_t)row * 512 + lane * 8;
    *(uint2*)base = H;
    *(uint2*)(base + 256) = L;
}

__device__ __forceinline__ void load_hl(
    const __nv_bfloat16* fi, int row, int lane,
    float& r0, float& r1, float& r2, float& r3)
{
    const char* base = (const char*)fi + (size_t)row * 512 + lane * 8;
    uint2 H = __ldcs((const uint2*)base);
    uint2 L = __ldcs((const uint2*)(base + 256));
    __nv_bfloat162 h0 = *(__nv_bfloat162*)&H.x;
    __nv_bfloat162 h1 = *(__nv_bfloat162*)&H.y;
    __nv_bfloat162 l0 = *(__nv_bfloat162*)&L.x;
    __nv_bfloat162 l1 = *(__nv_bfloat162*)&L.y;
    r0 = __bfloat162float(h0.x) + __bfloat162float(l0.x);
    r1 = __bfloat162float(h0.y) + __bfloat162float(l0.y);
    r2 = __bfloat162float(h1.x) + __bfloat162float(l1.x);
    r3 = __bfloat162float(h1.y) + __bfloat162float(l1.y);
}

__device__ __forceinline__ float4 gn_row(float4 v, float4 g, float4 b) {
    float s1 = v.x + v.y + v.z + v.w;
    float s2 = v.x * v.x + v.y * v.y + v.z * v.z + v.w * v.w;
    #pragma unroll
    for (int o = 16; o >= 1; o >>= 1) {
        s1 += __shfl_xor_sync(0xffffffffu, s1, o);
        s2 += __shfl_xor_sync(0xffffffffu, s2, o);
    }
    float mu = s1 * (1.f / 128.f);
    float var = s2 * (1.f / 128.f) - mu * mu;
    float rs = rsqrtf(var + 1e-5f);
    return make_float4((v.x - mu) * rs * g.x + b.x, (v.y - mu) * rs * g.y + b.y,
                       (v.z - mu) * rs * g.z + b.z, (v.w - mu) * rs * g.w + b.w);
}

// ================= dense bf16x3 GEMM =================
__device__ __forceinline__ void stage_q_d(
    u32 smb, int q, int bi, int tid, int row0, int nrows,
    const __nv_bfloat16* Ahl,
    const __nv_bfloat16* WH, const __nv_bfloat16* WL)
{
    u32 bbase = smb + (u32)bi * QSET;
    #pragma unroll
    for (int j = 0; j < 2; j++) {
        int id = tid + j * 256;
        int r = id >> 2, sg = id & 3;
        u32 doff = swz(r, sg);
        u32 asz = 16;
        int gr = row0 + r;
        if (gr >= nrows) { asz = 0; gr = 0; }
        size_t abyte = (size_t)gr * 512 + (size_t)q * 64 + (size_t)sg * 16;
        cpa16(bbase + OFF_AH + doff, (const char*)Ahl + abyte, asz);
        cpa16(bbase + OFF_AL + doff, (const char*)Ahl + abyte + 256, asz);
        size_t wbyte = (size_t)r * 256 + (size_t)q * 64 + (size_t)sg * 16;
        cpa16(bbase + OFF_BH + doff, (const char*)WH + wbyte, 16);
        cpa16(bbase + OFF_BL + doff, (const char*)WL + wbyte, 16);
    }
    CP_COMMIT();
}

// EPI: 0 fp32 store (shuffle epilogue, streaming) | 3 extras + GN + relu + split
template<int EPI>
__global__ __launch_bounds__(256, 2) void hmma_gemm(
    const __nv_bfloat16* __restrict__ Ahl,
    const __nv_bfloat16* __restrict__ Whi, const __nv_bfloat16* __restrict__ Wlo,
    float* __restrict__ out,
    const float* __restrict__ gng, const float* __restrict__ gnb,
    __nv_bfloat16* __restrict__ fo,
    int nrows,
    const float* __restrict__ turn, const float* __restrict__ control,
    const float* __restrict__ inter, const float* __restrict__ wext)
{
    extern __shared__ char dsm[];
    const int tid = threadIdx.x;
    const int wid = tid >> 5;
    const int lane = tid & 31;
    const int row0 = blockIdx.x * 128;
    const u32 smb = cvta_sm(dsm);

    const int wm = (wid & 3) * 32;
    const int wn = (wid >> 2) * 64;

    float acc[2][8][4];
    #pragma unroll
    for (int mi = 0; mi < 2; mi++)
        #pragma unroll
        for (int nj = 0; nj < 8; nj++)
            #pragma unroll
            for (int q = 0; q < 4; q++) acc[mi][nj][q] = 0.f;

    const int ra = wm + (lane & 15);
    const u32 xa = (u32)((ra >> 1) & 3);
    const int ca = lane >> 4;
    const int rb = wn + (lane & 7) + ((lane >> 4) & 1) * 8;
    const u32 xb = (u32)((rb >> 1) & 3);
    const int cb = (lane >> 3) & 1;

    stage_q_d(smb, 0, 0, tid, row0, nrows, Ahl, Whi, Wlo);
    stage_q_d(smb, 1, 1, tid, row0, nrows, Ahl, Whi, Wlo);
    stage_q_d(smb, 2, 2, tid, row0, nrows, Ahl, Whi, Wlo);

    #pragma unroll
    for (int q = 0; q < 4; q++) {
        if (q <= 1)      asm volatile("cp.async.wait_group 2;" ::: "memory");
        else if (q == 2) asm volatile("cp.async.wait_group 1;" ::: "memory");
        else             asm volatile("cp.async.wait_group 0;" ::: "memory");
        __syncthreads();

        const u32 qb = smb + (u32)(q % 3) * QSET;
        #pragma unroll
        for (int ks = 0; ks < 2; ks++) {
            const u32 ach = (u32)(ks * 2 + ca) ^ xa;
            const u32 bch = (u32)(ks * 2 + cb) ^ xb;
            const u32 aoff = (u32)ra * 64u + (ach << 4);
            u32 a0[2][4], a1[2][4], b0[4][4], b1[4][4];
            ldm4(a0[0], qb + OFF_AH + aoff);
            ldm4(a0[1], qb + OFF_AH + aoff + 16 * 64);
            #pragma unroll
            for (int ni = 0; ni < 4; ni++)
                ldm4(b0[ni], qb + OFF_BH + (u32)(rb + ni * 16) * 64u + (bch << 4));
            MMAS(a0, b0);
            ldm4(a1[0], qb + OFF_AL + aoff);
            ldm4(a1[1], qb + OFF_AL + aoff + 16 * 64);
            MMAS(a1, b0);
            #pragma unroll
            for (int ni = 0; ni < 4; ni++)
                ldm4(b1[ni], qb + OFF_BL + (u32)(rb + ni * 16) * 64u + (bch << 4));
            MMAS(a0, b1);
        }

        if (q == 0) {
            __syncthreads();
            stage_q_d(smb, 3, 0, tid, row0, nrows, Ahl, Whi, Wlo);
        }
    }

    if (EPI == 0) {
        // direct fragment -> STG (streaming) via pair shuffle
        #pragma unroll
        for (int mi = 0; mi < 2; mi++) {
            int r_e = row0 + wm + mi * 16 + (lane >> 2);
            int r_o = r_e + 8;
            int cbx = wn + ((lane >> 1) & 1) * 4;
            #pragma unroll
            for (int nj = 0; nj < 8; nj++) {
                float x0 = acc[mi][nj][0], x1 = acc[mi][nj][1];
                float y0 = acc[mi][nj][2], y1 = acc[mi][nj][3];
                float px0 = __shfl_xor_sync(0xffffffffu, x0, 1);
                float px1 = __shfl_xor_sync(0xffffffffu, x1, 1);
                float py0 = __shfl_xor_sync(0xffffffffu, y0, 1);
                float py1 = __shfl_xor_sync(0xffffffffu, y1, 1);
                int cc = cbx + nj * 8;
                if ((lane & 1) == 0) {
                    if (r_e < nrows)
                        __stcs((float4*)(out + (size_t)r_e * C + cc),
                               make_float4(x0, x1, px0, px1));
                } else {
                    if (r_o < nrows)
                        __stcs((float4*)(out + (size_t)r_o * C + cc),
                               make_float4(py0, py1, y0, y1));
                }
            }
        }
        return;
    }

    // ---- EPI 3: smem C-tile + row-wise epilogue ----
    __syncthreads();
    float* Csm = (float*)dsm;
    #pragma unroll
    for (int mi = 0; mi < 2; mi++)
        #pragma unroll
        for (int nj = 0; nj < 8; nj++) {
            int r = wm + mi * 16 + (lane >> 2);
            int c = wn + nj * 8 + (lane & 3) * 2;
            float* p = Csm + (size_t)r * LDC + c;
            p[0] = acc[mi][nj][0];
            p[1] = acc[mi][nj][1];
            p[8 * LDC] = acc[mi][nj][2];
            p[8 * LDC + 1] = acc[mi][nj][3];
        }
    __syncthreads();

    float4 gv = *(const float4*)(gng + lane * 4);
    float4 bv = *(const float4*)(gnb + lane * 4);
    float4 we[4];
    #pragma unroll
    for (int j = 0; j < 4; j++)
        we[j] = *(const float4*)(wext + (size_t)j * C + lane * 4);

    for (int i = 0; i < 16; i++) {
        int r = wid * 16 + i;
        int row = row0 + r;
        if (row >= nrows) continue;
        float4 v = *(float4*)(Csm + (size_t)r * LDC + lane * 4);
        float t0 = turn[2 * row], t1 = turn[2 * row + 1];
        float cc0 = control[row], it = inter[row];
        v.x += t0 * we[0].x + t1 * we[1].x + cc0 * we[2].x + it * we[3].x;
        v.y += t0 * we[0].y + t1 * we[1].y + cc0 * we[2].y + it * we[3].y;
        v.z += t0 * we[0].z + t1 * we[1].z + cc0 * we[2].z + it * we[3].z;
        v.w += t0 * we[0].w + t1 * we[1].w + cc0 * we[2].w + it * we[3].w;
        float4 o = gn_row(v, gv, bv);
        store_split(fo, row, lane, fmaxf(o.x, 0.f), fmaxf(o.y, 0.f),
                    fmaxf(o.z, 0.f), fmaxf(o.w, 0.f));
    }
}

// ============ edge GEMM: all pre/suc/left/right in one launch, RED into T ========
// src indices in registers (no entry sync); smem C-tile RED epilogue.
__global__ __launch_bounds__(256, 2) void edge_gemm(
    const __nv_bfloat16* __restrict__ Ahl,
    const __nv_bfloat16* __restrict__ Whi, const __nv_bfloat16* __restrict__ Wlo,
    float* __restrict__ T,
    const int* __restrict__ pre, const int* __restrict__ suc,
    const int* __restrict__ left, const int* __restrict__ right,
    int layer)
{
    const int y = blockIdx.y;
    const int* dbase;
    int nedges;
    size_t wslot;
    if (y < 6) {
        dbase = pre + (size_t)y * 2 * EP; nedges = EP;
        wslot = OFF_PS + (size_t)(layer * 12 + y) * CC;
    } else if (y < 12) {
        dbase = suc + (size_t)(y - 6) * 2 * EP; nedges = EP;
        wslot = OFF_PS + (size_t)(layer * 12 + y) * CC;
    } else {
        if (blockIdx.x >= 196) return;
        dbase = (y == 12) ? left : right; nedges = EL;
        wslot = OFF_LR + (size_t)(layer * 2 + (y - 12)) * CC;
    }
    const int* sbase = dbase + nedges;

    extern __shared__ char dsm[];
    const int tid = threadIdx.x;
    const int wid = tid >> 5;
    const int lane = tid & 31;
    const u32 smb = cvta_sm(dsm);
    int* s_dst = (int*)(dsm + SM_IDX);

    const __nv_bfloat16* WH = Whi + wslot;
    const __nv_bfloat16* WL = Wlo + wslot;

    // per-thread src indices for staging rows (tid>>2) and (tid>>2)+64
    const int e_base = blockIdx.x * 128;
    int er0 = e_base + (tid >> 2);
    int er1 = er0 + 64;
    const long long src0 = (er0 < nedges) ? sbase[er0] : 0;
    const long long src1 = (er1 < nedges) ? sbase[er1] : 0;
    // dst indices to smem (visibility guaranteed by mainloop barriers)
    if (tid < 128) {
        int e = e_base + tid;
        s_dst[tid] = (e < nedges) ? dbase[e] : -1;
    }

    const int wm = (wid & 3) * 32;
    const int wn = (wid >> 2) * 64;

    float acc[2][8][4];
    #pragma unroll
    for (int mi = 0; mi < 2; mi++)
        #pragma unroll
        for (int nj = 0; nj < 8; nj++)
            #pragma unroll
            for (int q = 0; q < 4; q++) acc[mi][nj][q] = 0.f;

    const int ra = wm + (lane & 15);
    const u32 xa = (u32)((ra >> 1) & 3);
    const int ca = lane >> 4;
    const int rb = wn + (lane & 7) + ((lane >> 4) & 1) * 8;
    const u32 xb = (u32)((rb >> 1) & 3);
    const int cb = (lane >> 3) & 1;

    #define STAGE_QG(qq, bi) do {                                              \
        u32 bbase_ = smb + (u32)(bi) * QSET;                                   \
        _Pragma("unroll") for (int j = 0; j < 2; j++) {                        \
            int id = tid + j * 256;                                            \
            int r = id >> 2, sg = id & 3;                                      \
            u32 doff = swz(r, sg);                                             \
            long long sr = j ? src1 : src0;                                    \
            size_t abyte = (size_t)sr * 512 + (size_t)(qq) * 64 + (size_t)sg * 16; \
            cpa16(bbase_ + OFF_AH + doff, (const char*)Ahl + abyte, 16);       \
            cpa16(bbase_ + OFF_AL + doff, (const char*)Ahl + abyte + 256, 16); \
            size_t wbyte = (size_t)r * 256 + (size_t)(qq) * 64 + (size_t)sg * 16; \
            cpa16(bbase_ + OFF_BH + doff, (const char*)WH + wbyte, 16);        \
            cpa16(bbase_ + OFF_BL + doff, (const char*)WL + wbyte, 16);        \
        }                                                                      \
        CP_COMMIT();                                                           \
    } while (0)

    STAGE_QG(0, 0);
    STAGE_QG(1, 1);
    STAGE_QG(2, 2);

    #pragma unroll
    for (int q = 0; q < 4; q++) {
        if (q <= 1)      asm volatile("cp.async.wait_group 2;" ::: "memory");
        else if (q == 2) asm volatile("cp.async.wait_group 1;" ::: "memory");
        else             asm volatile("cp.async.wait_group 0;" ::: "memory");
        __syncthreads();

        const u32 qb = smb + (u32)(q % 3) * QSET;
        #pragma unroll
        for (int ks = 0; ks < 2; ks++) {
            const u32 ach = (u32)(ks * 2 + ca) ^ xa;
            const u32 bch = (u32)(ks * 2 + cb) ^ xb;
            const u32 aoff = (u32)ra * 64u + (ach << 4);
            u32 a0[2][4], a1[2][4], b0[4][4], b1[4][4];
            ldm4(a0[0], qb + OFF_AH + aoff);
            ldm4(a0[1], qb + OFF_AH + aoff + 16 * 64);
            #pragma unroll
            for (int ni = 0; ni < 4; ni++)
                ldm4(b0[ni], qb + OFF_BH + (u32)(rb + ni * 16) * 64u + (bch << 4));
            MMAS(a0, b0);
            ldm4(a1[0], qb + OFF_AL + aoff);
            ldm4(a1[1], qb + OFF_AL + aoff + 16 * 64);
            MMAS(a1, b0);
            #pragma unroll
            for (int ni = 0; ni < 4; ni++)
                ldm4(b1[ni], qb + OFF_BL + (u32)(rb + ni * 16) * 64u + (bch << 4));
            MMAS(a0, b1);
        }

        if (q == 0) {
            __syncthreads();
            STAGE_QG(3, 0);
        }
    }
    #undef STAGE_QG

    __syncthreads();
    float* Csm = (float*)dsm;
    #pragma unroll
    for (int mi = 0; mi < 2; mi++)
        #pragma unroll
        for (int nj = 0; nj < 8; nj++) {
            int r = wm + mi * 16 + (lane >> 2);
            int c = wn + nj * 8 + (lane & 3) * 2;
            float* p = Csm + (size_t)r * LDC + c;
            p[0] = acc[mi][nj][0];
            p[1] = acc[mi][nj][1];
            p[8 * LDC] = acc[mi][nj][2];
            p[8 * LDC + 1] = acc[mi][nj][3];
        }
    __syncthreads();

    for (int i = 0; i < 16; i++) {
        int r = wid * 16 + i;
        int dd = s_dst[r];
        if (dd < 0) continue;
        float4 v = *(float4*)(Csm + (size_t)r * LDC + lane * 4);
        red4(T + (size_t)dd * C + lane * 4, v.x, v.y, v.z, v.w);
    }
}

// ======== gn_gemm: A = relu(gn(T)) in-kernel, C = A @ W, residual from bf16 hi/lo ==
#define G_AH   0
#define G_AL   32768
#define G_B    65536
#define G_DSM  98304

__global__ __launch_bounds__(256, 2) void gn_gemm(
    const float* __restrict__ Tg,
    const float* __restrict__ ing, const float* __restrict__ inb,
    const __nv_bfloat16* __restrict__ Whi, const __nv_bfloat16* __restrict__ Wlo,
    float* __restrict__ wout,
    const float* __restrict__ outg, const float* __restrict__ outb,
    const __nv_bfloat16* __restrict__ addhl,
    __nv_bfloat16* __restrict__ fo,
    int nrows)
{
    extern __shared__ char dsm[];
    const int tid = threadIdx.x;
    const int wid = tid >> 5;
    const int lane = tid & 31;
    const int row0 = blockIdx.x * 128;
    const u32 smb = cvta_sm(dsm);

    #define STAGE_B2(qq, bi) do {                                              \
        u32 bb_ = smb + G_B + (u32)(bi) * 16384u;                              \
        _Pragma("unroll") for (int j = 0; j < 2; j++) {                        \
            int id = tid + j * 256;                                            \
            int r = id >> 2, sg = id & 3;                                      \
            u32 doff = swz(r, sg);                                             \
            size_t wbyte = (size_t)r * 256 + (size_t)(qq) * 64 + (size_t)sg * 16; \
            cpa16(bb_ + doff, (const char*)Whi + wbyte, 16);                   \
            cpa16(bb_ + 8192u + doff, (const char*)Wlo + wbyte, 16);           \
        }                                                                      \
        CP_COMMIT();                                                           \
    } while (0)

    STAGE_B2(0, 0);
    STAGE_B2(1, 1);

    {
        float4 gin = *(const float4*)(ing + lane * 4);
        float4 bin = *(const float4*)(inb + lane * 4);
        const int q  = lane >> 3;
        const int c  = (lane >> 1) & 3;
        const int o8 = (lane & 1) * 8;
        #pragma unroll 4
        for (int it = 0; it < 16; it++) {
            int r = wid + it * 8;
            int row = row0 + r;
            float4 v = make_float4(0.f, 0.f, 0.f, 0.f);
            if (row < nrows) v = __ldcs((const float4*)(Tg + (size_t)row * C + lane * 4));
            float4 o = gn_row(v, gin, bin);
            float v0 = fmaxf(o.x, 0.f), v1 = fmaxf(o.y, 0.f);
            float v2 = fmaxf(o.z, 0.f), v3 = fmaxf(o.w, 0.f);
            __nv_bfloat16 h0 = __float2bfloat16(v0), h1 = __float2bfloat16(v1);
            __nv_bfloat16 h2 = __float2bfloat16(v2), h3 = __float2bfloat16(v3);
            __nv_bfloat162 hh0; hh0.x = h0; hh0.y = h1;
            __nv_bfloat162 hh1; hh1.x = h2; hh1.y = h3;
            uint2 H; H.x = *(u32*)&hh0; H.y = *(u32*)&hh1;
            uint2 L;
            L.x = pack_bf2(v0 - __bfloat162float(h0), v1 - __bfloat162float(h1));
            L.y = pack_bf2(v2 - __bfloat162float(h2), v3 - __bfloat162float(h3));
            u32 off = (u32)q * 8192u + swz(r, c) + (u32)o8;
            *(uint2*)(dsm + G_AH + off) = H;
            *(uint2*)(dsm + G_AL + off) = L;
        }
    }

    const int wm = (wid & 3) * 32;
    const int wn = (wid >> 2) * 64;

    float acc[2][8][4];
    #pragma unroll
    for (int mi = 0; mi < 2; mi++)
        #pragma unroll
        for (int nj = 0; nj < 8; nj++)
            #pragma unroll
            for (int q = 0; q < 4; q++) acc[mi][nj][q] = 0.f;

    const int ra = wm + (lane & 15);
    const u32 xa = (u32)((ra >> 1) & 3);
    const int ca = lane >> 4;
    const int rb = wn + (lane & 7) + ((lane >> 4) & 1) * 8;
    const u32 xb = (u32)((rb >> 1) & 3);
    const int cb = (lane >> 3) & 1;

    #pragma unroll
    for (int q = 0; q < 4; q++) {
        if (q < 3) asm volatile("cp.async.wait_group 1;" ::: "memory");
        else       asm volatile("cp.async.wait_group 0;" ::: "memory");
        __syncthreads();

        const u32 aqh = smb + G_AH + (u32)q * 8192u;
        const u32 aql = smb + G_AL + (u32)q * 8192u;
        const u32 bqh = smb + G_B + (u32)(q & 1) * 16384u;
        const u32 bql = bqh + 8192u;
        #pragma unroll
        for (int ks = 0; ks < 2; ks++) {
            const u32 ach = (u32)(ks * 2 + ca) ^ xa;
            const u32 bch = (u32)(ks * 2 + cb) ^ xb;
            const u32 aoff = (u32)ra * 64u + (ach << 4);
            u32 a0[2][4], a1[2][4], b0[4][4], b1[4][4];
            ldm4(a0[0], aqh + aoff);
            ldm4(a0[1], aqh + aoff + 16 * 64);
            #pragma unroll
            for (int ni = 0; ni < 4; ni++)
                ldm4(b0[ni], bqh + (u32)(rb + ni * 16) * 64u + (bch << 4));
            MMAS(a0, b0);
            ldm4(a1[0], aql + aoff);
            ldm4(a1[1], aql + aoff + 16 * 64);
            MMAS(a1, b0);
            #pragma unroll
            for (int ni = 0; ni < 4; ni++)
                ldm4(b1[ni], bql + (u32)(rb + ni * 16) * 64u + (bch << 4));
            MMAS(a0, b1);
        }

        if (q < 2) {
            __syncthreads();
            STAGE_B2(q + 2, q & 1);
        }
    }
    #undef STAGE_B2

    __syncthreads();
    float* Csm = (float*)dsm;
    #pragma unroll
    for (int mi = 0; mi < 2; mi++)
        #pragma unroll
        for (int nj = 0; nj < 8; nj++) {
            int r = wm + mi * 16 + (lane >> 2);
            int c = wn + nj * 8 + (lane & 3) * 2;
            float* p = Csm + (size_t)r * LDC + c;
            p[0] = acc[mi][nj][0];
            p[1] = acc[mi][nj][1];
            p[8 * LDC] = acc[mi][nj][2];
            p[8 * LDC + 1] = acc[mi][nj][3];
        }
    __syncthreads();

    float4 gv = *(const float4*)(outg + lane * 4);
    float4 bv = *(const float4*)(outb + lane * 4);

    for (int i = 0; i < 16; i++) {
        int r = wid * 16 + i;
        int row = row0 + r;
        if (row >= nrows) continue;
        float4 v = *(float4*)(Csm + (size_t)r * LDC + lane * 4);
        float4 o = gn_row(v, gv, bv);
        float r0, r1, r2, r3;
        load_hl(addhl, row, lane, r0, r1, r2, r3);
        float v0 = fmaxf(o.x + r0, 0.f);
        float v1 = fmaxf(o.y + r1, 0.f);
        float v2 = fmaxf(o.z + r2, 0.f);
        float v3 = fmaxf(o.w + r3, 0.f);
        if (wout)
            *(float4*)(wout + (size_t)row * C + lane * 4) = make_float4(v0, v1, v2, v3);
        store_split(fo, row, lane, v0, v1, v2, v3);
    }
}

// ======== dual_gemm: fused prologue in2+seg2 =========================
#define D_QA  0
#define D_QB  16384
#define D_QSET 49152
#define D_DSM  98304
#define LDC64  132

__global__ __launch_bounds__(256, 2) void dual_gemm(
    const __nv_bfloat16* __restrict__ H1, const __nv_bfloat16* __restrict__ H2,
    const __nv_bfloat16* __restrict__ Whi, const __nv_bfloat16* __restrict__ Wlo,
    const float* __restrict__ g1, const float* __restrict__ b1,
    const float* __restrict__ g2, const float* __restrict__ b2,
    __nv_bfloat16* __restrict__ fo, int nrows)
{
    extern __shared__ char dsm[];
    const int tid = threadIdx.x;
    const int wid = tid >> 5;
    const int lane = tid & 31;
    const int row0 = blockIdx.x * 64;
    const u32 smb = cvta_sm(dsm);

    const __nv_bfloat16* W1h = Whi + OFF_IN2;
    const __nv_bfloat16* W1l = Wlo + OFF_IN2;
    const __nv_bfloat16* W2h = Whi + OFF_SEG2;
    const __nv_bfloat16* W2l = Wlo + OFF_SEG2;

    #define STAGE_D(qq, bi) do {                                               \
        u32 qa_ = smb + (u32)(bi) * D_QSET + D_QA;                             \
        u32 qb_ = smb + (u32)(bi) * D_QSET + D_QB;                             \
        {                                                                      \
            int r = tid >> 2, sg = tid & 3;                                    \
            u32 doff = swz(r, sg);                                             \
            u32 asz = 16;                                                      \
            int gr = row0 + r;                                                 \
            if (gr >= nrows) { asz = 0; gr = 0; }                              \
            size_t ab = (size_t)gr * 512 + (size_t)(qq) * 64 + (size_t)sg * 16; \
            cpa16(qa_ + 0u     + doff, (const char*)H1 + ab, asz);             \
            cpa16(qa_ + 4096u  + doff, (const char*)H1 + ab + 256, asz);       \
            cpa16(qa_ + 8192u  + doff, (const char*)H2 + ab, asz);             \
            cpa16(qa_ + 12288u + doff, (const char*)H2 + ab + 256, asz);       \
        }                                                                      \
        _Pragma("unroll") for (int j = 0; j < 2; j++) {                        \
            int id = tid + j * 256;                                            \
            int r = id >> 2, sg = id & 3;                                      \
            u32 doff = swz(r, sg);                                             \
            size_t wb = (size_t)r * 256 + (size_t)(qq) * 64 + (size_t)sg * 16; \
            cpa16(qb_ + 0u      + doff, (const char*)W1h + wb, 16);            \
            cpa16(qb_ + 8192u   + doff, (const char*)W1l + wb, 16);            \
            cpa16(qb_ + 16384u  + doff, (const char*)W2h + wb, 16);            \
            cpa16(qb_ + 24576u  + doff, (const char*)W2l + wb, 16);            \
        }                                                                      \
        CP_COMMIT();                                                           \
    } while (0)

    STAGE_D(0, 0);
    STAGE_D(1, 1);

    const int wm = (wid & 3) * 16;
    const int wn = (wid >> 2) * 64;

    float accP[8][4], accQ[8][4];
    #pragma unroll
    for (int nj = 0; nj < 8; nj++)
        #pragma unroll
        for (int q = 0; q < 4; q++) { accP[nj][q] = 0.f; accQ[nj][q] = 0.f; }

    const int ra = wm + (lane & 15);
    const u32 xa = (u32)((ra >> 1) & 3);
    const int ca = lane >> 4;
    const int rb = wn + (lane & 7) + ((lane >> 4) & 1) * 8;
    const u32 xb = (u32)((rb >> 1) & 3);
    const int cb = (lane >> 3) & 1;

    #pragma unroll
    for (int q = 0; q < 4; q++) {
        if (q < 3) asm volatile("cp.async.wait_group 1;" ::: "memory");
        else       asm volatile("cp.async.wait_group 0;" ::: "memory");
        __syncthreads();

        const u32 qa = smb + (u32)(q & 1) * D_QSET + D_QA;
        const u32 qb = smb + (u32)(q & 1) * D_QSET + D_QB;
        #pragma unroll
        for (int ks = 0; ks < 2; ks++) {
            const u32 ach = (u32)(ks * 2 + ca) ^ xa;
            const u32 bch = (u32)(ks * 2 + cb) ^ xb;
            const u32 aoff = (u32)ra * 64u + (ach << 4);
            u32 a0[4], a1[4], b0[4][4], b1[4][4];
            ldm4(a0, qa + aoff);
            #pragma unroll
            for (int ni = 0; ni < 4; ni++)
                ldm4(b0[ni], qb + (u32)(rb + ni * 16) * 64u + (bch << 4));
            MMAS1(accP, a0, b0);
            ldm4(a1, qa + 4096u + aoff);
            MMAS1(accP, a1, b0);
            #pragma unroll
            for (int ni = 0; ni < 4; ni++)
                ldm4(b1[ni], qb + 8192u + (u32)(rb + ni * 16) * 64u + (bch << 4));
            MMAS1(accP, a0, b1);
            ldm4(a0, qa + 8192u + aoff);
            #pragma unroll
            for (int ni = 0; ni < 4; ni++)
                ldm4(b0[ni], qb + 16384u + (u32)(rb + ni * 16) * 64u + (bch << 4));
            MMAS1(accQ, a0, b0);
            ldm4(a1, qa + 12288u + aoff);
            MMAS1(accQ, a1, b0);
            #pragma unroll
            for (int ni = 0; ni < 4; ni++)
                ldm4(b1[ni], qb + 24576u + (u32)(rb + ni * 16) * 64u + (bch << 4));
            MMAS1(accQ, a0, b1);
        }

        if (q < 2) {
            __syncthreads();
            STAGE_D(q + 2, q & 1);
        }
    }
    #undef STAGE_D

    __syncthreads();
    float* CsmP = (float*)dsm;
    float* CsmQ = (float*)(dsm + 64 * LDC64 * 4);
    #pragma unroll
    for (int nj = 0; nj < 8; nj++) {
        int r = wm + (lane >> 2);
        int c = wn + nj * 8 + (lane & 3) * 2;
        float* p = CsmP + (size_t)r * LDC64 + c;
        p[0] = accP[nj][0]; p[1] = accP[nj][1];
        p[8 * LDC64] = accP[nj][2]; p[8 * LDC64 + 1] = accP[nj][3];
        float* qp = CsmQ + (size_t)r * LDC64 + c;
        qp[0] = accQ[nj][0]; qp[1] = accQ[nj][1];
        qp[8 * LDC64] = accQ[nj][2]; qp[8 * LDC64 + 1] = accQ[nj][3];
    }
    __syncthreads();

    float4 g1v = *(const float4*)(g1 + lane * 4);
    float4 b1v = *(const float4*)(b1 + lane * 4);
    float4 g2v = *(const float4*)(g2 + lane * 4);
    float4 b2v = *(const float4*)(b2 + lane * 4);

    for (int i = 0; i < 8; i++) {
        int r = wid * 8 + i;
        int row = row0 + r;
        if (row >= nrows) continue;
        float4 vp = *(float4*)(CsmP + (size_t)r * LDC64 + lane * 4);
        float4 vq = *(float4*)(CsmQ + (size_t)r * LDC64 + lane * 4);
        float4 a = gn_row(vp, g1v, b1v);
        float4 b = gn_row(vq, g2v, b2v);
        store_split(fo, row, lane,
                    fmaxf(a.x + b.x, 0.f), fmaxf(a.y + b.y, 0.f),
                    fmaxf(a.z + b.z, 0.f), fmaxf(a.w + b.w, 0.f));
    }
}

// ================= fused prep kernel =================
#define PREP_COPY_B 1563
#define PREP_W_B    4288
#define PREP_IN_B   25000

__global__ void prep(
    const float* __restrict__ ctrs, const float* __restrict__ feats,
    const float* __restrict__ w_in1, const float* __restrict__ b_in1,
    const float* __restrict__ w_seg1, const float* __restrict__ b_seg1,
    const float* __restrict__ w_in2, const float* __restrict__ w_seg2,
    const float* __restrict__ w_meta,
    const float* __restrict__ ctr_w, const float* __restrict__ pre_w,
    const float* __restrict__ suc_w, const float* __restrict__ left_w,
    const float* __restrict__ right_w, const float* __restrict__ ctr2_w,
    __nv_bfloat16* __restrict__ whi, __nv_bfloat16* __restrict__ wlo,
    __nv_bfloat16* __restrict__ h1, __nv_bfloat16* __restrict__ h2,
    float* __restrict__ out_tail)
{
    int b = blockIdx.x;
    int tid = threadIdx.x;
    if (b < PREP_COPY_B) {
        int i = b * 256 + tid;
        if (i < N_NODES * 2) out_tail[i] = ctrs[i];
        return;
    }
    b -= PREP_COPY_B;
    if (b < PREP_W_B) {
        int idx = b * 256 + tid;
        int mat = idx >> 14;
        int rem = idx & 16383;
        int k = rem >> 7, n = rem & 127;
        const float* src;
        if      (mat == 0) src = w_in2 + rem;
        else if (mat == 1) src = w_seg2 + rem;
        else if (mat == 2) src = w_meta + rem;
        else if (mat < 51) {
            int m = mat - 3; int i = m / 12; int r = m % 12;
            src = (r < 6) ? pre_w + (size_t)(i * 6 + r) * CC + rem
                          : suc_w + (size_t)(i * 6 + r - 6) * CC + rem;
        } else if (mat < 59) {
            int m = mat - 51; int i = m >> 1;
            src = ((m & 1) ? right_w : left_w) + (size_t)i * CC + rem;
        } else if (mat < 63) src = ctr_w  + (size_t)(mat - 59) * CC + rem;
        else                 src = ctr2_w + (size_t)(mat - 63) * CC + rem;
        float x = *src;
        __nv_bfloat16 h = __float2bfloat16(x);
        size_t o = (size_t)mat * CC + (size_t)n * C + k;
        whi[o] = h;
        wlo[o] = __float2bfloat16(x - __bfloat162float(h));
        return;
    }
    b -= PREP_W_B;
    {
        int i = b * 256 + tid;
        int n = i >> 5, lane = i & 31;
        float x0 = ctrs[2 * n], x1 = ctrs[2 * n + 1];
        float4 wa = *(const float4*)(w_in1 + lane * 4);
        float4 wb = *(const float4*)(w_in1 + C + lane * 4);
        float4 bb = *(const float4*)(b_in1 + lane * 4);
        float a0 = fmaxf(x0 * wa.x + x1 * wb.x + bb.x, 0.f);
        float a1 = fmaxf(x0 * wa.y + x1 * wb.y + bb.y, 0.f);
        float a2 = fmaxf(x0 * wa.z + x1 * wb.z + bb.z, 0.f);
        float a3 = fmaxf(x0 * wa.w + x1 * wb.w + bb.w, 0.f);
        store_split(h1, n, lane, a0, a1, a2, a3);
        float y0 = feats[2 * n], y1 = feats[2 * n + 1];
        float4 wc = *(const float4*)(w_seg1 + lane * 4);
        float4 wd = *(const float4*)(w_seg1 + C + lane * 4);
        float4 bd = *(const float4*)(b_seg1 + lane * 4);
        float c0 = fmaxf(y0 * wc.x + y1 * wd.x + bd.x, 0.f);
        float c1 = fmaxf(y0 * wc.y + y1 * wd.y + bd.y, 0.f);
        float c2 = fmaxf(y0 * wc.z + y1 * wd.z + bd.z, 0.f);
        float c3 = fmaxf(y0 * wc.w + y1 * wd.w + bd.w, 0.f);
        store_split(h2, n, lane, c0, c1, c2, c3);
    }
}

// ================= host launcher =================
extern "C" void kernel_launch(void* const* d_in, const int* in_sizes, int n_in,
                              void* d_out, int out_size)
{
    const float* control  = (const float*)d_in[0];
    const float* turn     = (const float*)d_in[1];
    const float* inter    = (const float*)d_in[2];
    const float* ctrs     = (const float*)d_in[3];
    const float* feats    = (const float*)d_in[4];
    const int*   pre      = (const int*)d_in[5];
    const int*   suc      = (const int*)d_in[6];
    const int*   left     = (const int*)d_in[7];
    const int*   right    = (const int*)d_in[8];
    const float* w_in1    = (const float*)d_in[9];
    const float* b_in1    = (const float*)d_in[10];
    const float* w_in2    = (const float*)d_in[11];
    const float* gn_in_g  = (const float*)d_in[12];
    const float* gn_in_b  = (const float*)d_in[13];
    const float* w_seg1   = (const float*)d_in[14];
    const float* b_seg1   = (const float*)d_in[15];
    const float* w_seg2   = (const float*)d_in[16];
    const float* gn_seg_g = (const float*)d_in[17];
    const float* gn_seg_b = (const float*)d_in[18];
    const float* w_meta   = (const float*)d_in[19];
    const float* gn_m_g   = (const float*)d_in[20];
    const float* gn_m_b   = (const float*)d_in[21];
    const float* ctr_w    = (const float*)d_in[22];
    const float* pre_w    = (const float*)d_in[23];
    const float* suc_w    = (const float*)d_in[24];
    const float* left_w   = (const float*)d_in[25];
    const float* right_w  = (const float*)d_in[26];
    const float* norm_g   = (const float*)d_in[27];
    const float* norm_b   = (const float*)d_in[28];
    const float* ctr2_w   = (const float*)d_in[29];
    const float* ctr2_g   = (const float*)d_in[30];
    const float* ctr2_b   = (const float*)d_in[31];

    float* T;
    __nv_bfloat16 *Fhl, *Xhl, *Whi, *Wlo;
    cudaGetSymbolAddress((void**)&T, g_T);
    cudaGetSymbolAddress((void**)&Fhl, g_Fhl);
    cudaGetSymbolAddress((void**)&Xhl, g_Xhl);
    cudaGetSymbolAddress((void**)&Whi, g_Whi);
    cudaGetSymbolAddress((void**)&Wlo, g_Wlo);

    cudaFuncSetAttribute(hmma_gemm<0>, cudaFuncAttributeMaxDynamicSharedMemorySize, DSM);
    cudaFuncSetAttribute(hmma_gemm<3>, cudaFuncAttributeMaxDynamicSharedMemorySize, DSM);
    cudaFuncSetAttribute(edge_gemm, cudaFuncAttributeMaxDynamicSharedMemorySize, DSM);
    cudaFuncSetAttribute(gn_gemm, cudaFuncAttributeMaxDynamicSharedMemorySize, G_DSM);
    cudaFuncSetAttribute(dual_gemm, cudaFuncAttributeMaxDynamicSharedMemorySize, D_DSM);

    const int NB = (N_NODES + 127) / 128;
    const int NB64 = (N_NODES + 63) / 64;
    const int NBP = (EP + 127) / 128;   // 782
    const float* wext = w_meta + 128 * C;

    prep<<<PREP_COPY_B + PREP_W_B + PREP_IN_B, 256>>>(
        ctrs, feats, w_in1, b_in1, w_seg1, b_seg1,
        w_in2, w_seg2, w_meta, ctr_w, pre_w, suc_w, left_w, right_w, ctr2_w,
        Whi, Wlo, Xhl, Fhl, (float*)d_out + (size_t)N_NODES * C);
    dual_gemm<<<NB64, 256, D_DSM>>>(Xhl, Fhl, Whi, Wlo,
        gn_in_g, gn_in_b, gn_seg_g, gn_seg_b, Xhl, N_NODES);
    hmma_gemm<3><<<NB, 256, DSM>>>(Xhl, Whi + OFF_META, Wlo + OFF_META,
        nullptr, gn_m_g, gn_m_b, Fhl, N_NODES,
        turn, control, inter, wext);

    for (int i = 0; i < 4; i++) {
        float* wout = (i == 3) ? (float*)d_out : nullptr;

        hmma_gemm<0><<<NB, 256, DSM>>>(
            Fhl, Whi + OFF_CTR + (size_t)i * CC, Wlo + OFF_CTR + (size_t)i * CC,
            T, nullptr, nullptr, nullptr, N_NODES,
            nullptr, nullptr, nullptr, nullptr);
        edge_gemm<<<dim3(NBP, 14), 256, DSM>>>(
            Fhl, Whi, Wlo, T, pre, suc, left, right, i);
        gn_gemm<<<NB, 256, G_DSM>>>(
            T, norm_g + (size_t)i * C, norm_b + (size_t)i * C,
            Whi + OFF_CTR2 + (size_t)i * CC, Wlo + OFF_CTR2 + (size_t)i * CC,
            wout, ctr2_g + (size_t)i * C, ctr2_b + (size_t)i * C, Fhl,
            Fhl, N_NODES);
    }
}